// round 11
// baseline (speedup 1.0000x reference)
#include <cuda_runtime.h>
#include <cuda_bf16.h>
#include <cstdint>

#define D     128
#define NA    16384
#define NC    16384
#define NE    524288
#define TR    64
#define NT    256
#define KC    16
#define TRE   64      // edges per block (2 row-groups x 32 rows, 2 col-halves; 4 warps)
#define NTE   128     // threads per edge block
#define EPS   1e-5f
#define AROW  132     // floats per Aex row (bank-conflict-free stride)

// ---------------------------------------------------------------------------
// device scratch (no allocation)
// ---------------------------------------------------------------------------
__device__ __align__(16) float g_qb[NA * D];      // relu(GN(agts@query_w)) @ ctx_w1[128:256]
__device__ __align__(16) float g_ctxc[NC * D];    // ctx @ ctx_w1[256:384]
__device__ __align__(16) float g_acc[NA * D];     // agts@agt_w + scattered edge output
__device__ __align__(16) uint32_t g_wt[3 * 16384];// tf32 W images, FRAGMENT-ORDERED

// ---------------------------------------------------------------------------
// helpers
// ---------------------------------------------------------------------------
__device__ __forceinline__ uint32_t smem_u32(const void* p) {
    uint32_t a;
    asm("{ .reg .u64 t; cvta.to.shared.u64 t, %1; cvt.u32.u64 %0, t; }" : "=r"(a) : "l"(p));
    return a;
}

__device__ __forceinline__ uint32_t f2tf(float x) {
    uint32_t u;
    asm("cvt.rna.tf32.f32 %0, %1;" : "=r"(u) : "f"(x));
    return u;
}

__device__ __forceinline__ void mma_tf32(float c[4], const uint32_t a[4], uint32_t b0, uint32_t b1) {
    asm volatile(
        "mma.sync.aligned.m16n8k8.row.col.f32.tf32.tf32.f32 "
        "{%0,%1,%2,%3}, {%4,%5,%6,%7}, {%8,%9}, {%0,%1,%2,%3};"
        : "+f"(c[0]), "+f"(c[1]), "+f"(c[2]), "+f"(c[3])
        : "r"(a[0]), "r"(a[1]), "r"(a[2]), "r"(a[3]), "r"(b0), "r"(b1));
}

__device__ __forceinline__ uint32_t lds32(uint32_t a) {
    uint32_t v;
    asm volatile("ld.shared.b32 %0, [%1];" : "=r"(v) : "r"(a));
    return v;
}
__device__ __forceinline__ void lds128v(uint32_t r[4], uint32_t a) {
    asm volatile("ld.shared.v4.b32 {%0,%1,%2,%3}, [%4];"
                 : "=r"(r[0]), "=r"(r[1]), "=r"(r[2]), "=r"(r[3]) : "r"(a));
}
__device__ __forceinline__ void sts64(uint32_t a, uint32_t x, uint32_t y) {
    asm volatile("st.shared.v2.b32 [%0], {%1, %2};" :: "r"(a), "r"(x), "r"(y) : "memory");
}

__device__ __forceinline__ void red4(float* p, float a, float b, float c, float d) {
    asm volatile("red.global.add.v4.f32 [%0], {%1,%2,%3,%4};"
                 :: "l"(p), "f"(a), "f"(b), "f"(c), "f"(d) : "memory");
}

__device__ __forceinline__ void cp16(uint32_t daddr, const void* g) {
    asm volatile("cp.async.cg.shared.global [%0], [%1], 16;" :: "r"(daddr), "l"(g) : "memory");
}
__device__ __forceinline__ void cp_commit() { asm volatile("cp.async.commit_group;" ::: "memory"); }
template <int N>
__device__ __forceinline__ void cp_wait() {
    asm volatile("cp.async.wait_group %0;" :: "n"(N) : "memory");
}

// ---------------------------------------------------------------------------
// k_edge smem map (bytes): single W buffer + 64-row Aex  (2 blocks/SM)
// ---------------------------------------------------------------------------
#define SM_W      0        /* 64KB tf32 W image */
#define SM_AEX    65536    /* 64 rows x AROW floats = 33792B */
#define SM_STATS  99328    /* 256 floats */
#define SM_HIS    100352
#define SM_WIS    100608
#define SM_D2     100864
#define SMEM_EDGE 101376

// Fragment-ordered W image: float index = nh*8192 + kc*512 + j*128 + lane*4 + e
//   lane = bn*4 + bk;  j = khalf*2 + (p>>2);  e = p&3
//   where k = kc*8 + khalf*4 + bk,  n = nh*64 + p*8 + bn
__global__ void k_prep(const float* __restrict__ w0, const float* __restrict__ w1,
                       const float* __restrict__ w2) {
    int m = blockIdx.y;
    const float* src = (m == 0) ? w0 : (m == 1 ? w1 : w2);
    int idx = blockIdx.x * 256 + threadIdx.x;    // k*128 + n
    int k = idx >> 7, n = idx & 127;
    int kc = k >> 3, kloc = k & 7, bk = kloc & 3, khalf = kloc >> 2;
    int nh = n >> 6, p = (n >> 3) & 7, bn = n & 7;
    int j = khalf * 2 + (p >> 2);
    int e = p & 3;
    int l = bn * 4 + bk;
    int dest = nh * 8192 + kc * 512 + j * 128 + l * 4 + e;
    g_wt[m * 16384 + dest] = f2tf(src[idx]);
}

// async copy W image m into smem (64KB: 32 x 16B per thread @128thr)
__device__ __forceinline__ void copy_w_async(int m, uint32_t sb, int tid) {
    const uint4* s4 = (const uint4*)(g_wt + m * 16384);
#pragma unroll
    for (int i = 0; i < 32; i++)
        cp16(sb + SM_W + (uint32_t)((i * 128 + tid) * 16), s4 + i * 128 + tid);
    cp_commit();
}

// C[2 mg][8 tiles][4] += A[32 rows] @ W; warp rows rg*32..+31, cols nh*64..+63
// B loads: 4x ld.shared.v4 per kc (fragment-ordered image), conflict-free.
__device__ __forceinline__ void mma_stage(float c[2][8][4], uint32_t sb, int rg, int nh, int l) {
    const int ar = l >> 2, ak = l & 3;
    const uint32_t a0base = sb + SM_AEX + (uint32_t)(((rg * 32 + ar) * AROW + ak) * 4);
    const uint32_t bbase = sb + SM_W + (uint32_t)(nh * 32768 + l * 16);
#pragma unroll
    for (int kc = 0; kc < 16; kc++) {
        uint32_t b[16];
        uint32_t bb = bbase + (uint32_t)(kc * 2048);
        lds128v(b + 0,  bb);          // b0 halves, p=0..3
        lds128v(b + 4,  bb + 512);    // b0 halves, p=4..7
        lds128v(b + 8,  bb + 1024);   // b1 halves, p=0..3
        lds128v(b + 12, bb + 1536);   // b1 halves, p=4..7
        uint32_t a[2][4];
#pragma unroll
        for (int mg = 0; mg < 2; mg++) {
            uint32_t aa = a0base + (uint32_t)(mg * 16 * AROW * 4 + kc * 32);
            a[mg][0] = lds32(aa);
            a[mg][2] = lds32(aa + 16);
            a[mg][1] = lds32(aa + 8 * AROW * 4);
            a[mg][3] = lds32(aa + 8 * AROW * 4 + 16);
        }
#pragma unroll
        for (int mg = 0; mg < 2; mg++)
#pragma unroll
            for (int p = 0; p < 8; p++)
                mma_tf32(c[mg][p], a[mg], b[p], b[8 + p]);
    }
}

// GN(+relu) epilogue: (gather) -> stats -> barrier (+issue next W) -> normalize
// -> Aex(tf32) -> cp_wait -> barrier
template <bool GATHER>
__device__ __forceinline__ void ep_gn(float c[2][8][4],
                                      const float* __restrict__ gamma,
                                      const float* __restrict__ beta,
                                      uint32_t sb, char* smem,
                                      const int* hi_s, const int* wi_s,
                                      int rg, int nh, int l, int tid, int next_m) {
    const int q = l & 3;
    const int ar = l >> 2;
    const int cb = nh * 64;

    if (GATHER) {
#pragma unroll
        for (int mg = 0; mg < 2; mg++) {
            int r0 = rg * 32 + mg * 16 + ar;
            const float* qA = g_qb   + hi_s[r0] * D + cb;
            const float* cA = g_ctxc + wi_s[r0] * D + cb;
            const float* qB = g_qb   + hi_s[r0 + 8] * D + cb;
            const float* cB = g_ctxc + wi_s[r0 + 8] * D + cb;
#pragma unroll
            for (int t = 0; t < 8; t++) {
                float2 a1 = __ldg((const float2*)(qA + t * 8) + q);
                float2 a2 = __ldg((const float2*)(cA + t * 8) + q);
                float2 b1 = __ldg((const float2*)(qB + t * 8) + q);
                float2 b2 = __ldg((const float2*)(cB + t * 8) + q);
                c[mg][t][0] += a1.x + a2.x;  c[mg][t][1] += a1.y + a2.y;
                c[mg][t][2] += b1.x + b2.x;  c[mg][t][3] += b1.y + b2.y;
            }
        }
    }
    float s[4] = {0.f, 0.f, 0.f, 0.f}, qs[4] = {0.f, 0.f, 0.f, 0.f};
#pragma unroll
    for (int mg = 0; mg < 2; mg++)
#pragma unroll
        for (int t = 0; t < 8; t++) {
            s[mg * 2]     += c[mg][t][0] + c[mg][t][1];
            qs[mg * 2]     = fmaf(c[mg][t][0], c[mg][t][0], fmaf(c[mg][t][1], c[mg][t][1], qs[mg * 2]));
            s[mg * 2 + 1] += c[mg][t][2] + c[mg][t][3];
            qs[mg * 2 + 1] = fmaf(c[mg][t][2], c[mg][t][2], fmaf(c[mg][t][3], c[mg][t][3], qs[mg * 2 + 1]));
        }
#pragma unroll
    for (int i = 0; i < 4; i++) {
        s[i]  += __shfl_xor_sync(~0u, s[i], 1);  s[i]  += __shfl_xor_sync(~0u, s[i], 2);
        qs[i] += __shfl_xor_sync(~0u, qs[i], 1); qs[i] += __shfl_xor_sync(~0u, qs[i], 2);
    }

    float* st = (float*)(smem + SM_STATS);   // [nh][sum(64) | sq(64)]
    if (q == 0) {
#pragma unroll
        for (int mg = 0; mg < 2; mg++) {
            int r0 = rg * 32 + mg * 16 + ar;
            st[nh * 128 + r0]          = s[mg * 2];
            st[nh * 128 + 64 + r0]     = qs[mg * 2];
            st[nh * 128 + r0 + 8]      = s[mg * 2 + 1];
            st[nh * 128 + 64 + r0 + 8] = qs[mg * 2 + 1];
        }
    }
    __syncthreads();   // stats visible; all W reads of this stage done

    if (next_m >= 0) copy_w_async(next_m, sb, tid);   // overlaps normalize below

#pragma unroll
    for (int mg = 0; mg < 2; mg++) {
        int rA = rg * 32 + mg * 16 + ar;
        int rB = rA + 8;
        float S   = st[rA] + st[128 + rA];
        float SQ  = st[64 + rA] + st[192 + rA];
        float Sb  = st[rB] + st[128 + rB];
        float SQb = st[64 + rB] + st[192 + rB];
        float mA = S  * (1.f / 128.f), vA = SQ  * (1.f / 128.f) - mA * mA, rsA = rsqrtf(vA + EPS);
        float mB = Sb * (1.f / 128.f), vB = SQb * (1.f / 128.f) - mB * mB, rsB = rsqrtf(vB + EPS);
#pragma unroll
        for (int t = 0; t < 8; t++) {
            int c0 = cb + t * 8 + q * 2;
            float g0 = __ldg(gamma + c0), g1 = __ldg(gamma + c0 + 1);
            float b0 = __ldg(beta + c0),  b1 = __ldg(beta + c0 + 1);
            float xA0 = fmaxf(fmaf((c[mg][t][0] - mA) * rsA, g0, b0), 0.f);
            float xA1 = fmaxf(fmaf((c[mg][t][1] - mA) * rsA, g1, b1), 0.f);
            float xB0 = fmaxf(fmaf((c[mg][t][2] - mB) * rsB, g0, b0), 0.f);
            float xB1 = fmaxf(fmaf((c[mg][t][3] - mB) * rsB, g1, b1), 0.f);
            sts64(sb + SM_AEX + (uint32_t)((rA * AROW + c0) * 4), f2tf(xA0), f2tf(xA1));
            sts64(sb + SM_AEX + (uint32_t)((rB * AROW + c0) * 4), f2tf(xB0), f2tf(xB1));
        }
    }
    cp_wait<0>();
    __syncthreads();   // Aex + next W visible
}

__global__ __launch_bounds__(NTE, 2) void k_edge_mma(
    const float* __restrict__ agt_ctrs, const float* __restrict__ ctx_ctrs,
    const int* __restrict__ hi, const int* __restrict__ wi,
    const float* __restrict__ dist_w1, const float* __restrict__ dist_b1,
    const float* __restrict__ dist_g2, const float* __restrict__ dist_b2,
    const float* __restrict__ ctx_g1, const float* __restrict__ ctx_b1) {
    extern __shared__ char smem[];
    const uint32_t sb = smem_u32(smem);
    const int tid = threadIdx.x;
    const int w = tid >> 5, l = tid & 31, q = l & 3;
    const int rg = w >> 1, nh = w & 1;         // row group 0-1 (32 rows), col half 0-1
    const int ar = l >> 2;

    copy_w_async(0, sb, tid);                  // W0 in flight

    int* hi_s = (int*)(smem + SM_HIS);
    int* wi_s = (int*)(smem + SM_WIS);
    float2* d2s = (float2*)(smem + SM_D2);
    const int e0 = blockIdx.x * TRE;
    if (tid < TRE) {
        int h = hi[e0 + tid], ww = wi[e0 + tid];
        hi_s[tid] = h; wi_s[tid] = ww;
        float2 ac = ((const float2*)agt_ctrs)[h];
        float2 cc = ((const float2*)ctx_ctrs)[ww];
        d2s[tid] = make_float2(ac.x - cc.x, ac.y - cc.y);
    }
    __syncthreads();                           // ids/d2 visible

    // initial A = relu(d2 @ dist_w1 + b1) -> Aex as tf32
    for (int idx = tid; idx < TRE * D; idx += NTE) {
        int row = idx >> 7, col = idx & 127;
        float2 dd = d2s[row];
        float x = fmaxf(fmaf(dd.x, __ldg(dist_w1 + col),
                     fmaf(dd.y, __ldg(dist_w1 + D + col), __ldg(dist_b1 + col))), 0.f);
        *(uint32_t*)(smem + SM_AEX + (row * AROW + col) * 4) = f2tf(x);
    }
    cp_wait<0>();                              // W0 done
    __syncthreads();                           // Aex + W0 visible

    float c[2][8][4];
    // ---- stage 1: @ dist_w2, GN(dist_g2,b2)+relu; prefetch W1 in epilogue ----
#pragma unroll
    for (int mg = 0; mg < 2; mg++)
#pragma unroll
        for (int t = 0; t < 8; t++)
            c[mg][t][0] = c[mg][t][1] = c[mg][t][2] = c[mg][t][3] = 0.f;
    mma_stage(c, sb, rg, nh, l);
    ep_gn<false>(c, dist_g2, dist_b2, sb, smem, hi_s, wi_s, rg, nh, l, tid, 1);

    // ---- stage 2: @ ctx_w1[0:128] + qb[hi] + ctxc[wi], GN(ctx_g1,b1)+relu ----
#pragma unroll
    for (int mg = 0; mg < 2; mg++)
#pragma unroll
        for (int t = 0; t < 8; t++)
            c[mg][t][0] = c[mg][t][1] = c[mg][t][2] = c[mg][t][3] = 0.f;
    mma_stage(c, sb, rg, nh, l);
    ep_gn<true>(c, ctx_g1, ctx_b1, sb, smem, hi_s, wi_s, rg, nh, l, tid, 2);

    // ---- stage 3: @ ctx_w2, scatter-add (smem-staged, shuffle-free) ----
#pragma unroll
    for (int mg = 0; mg < 2; mg++)
#pragma unroll
        for (int t = 0; t < 8; t++)
            c[mg][t][0] = c[mg][t][1] = c[mg][t][2] = c[mg][t][3] = 0.f;
    mma_stage(c, sb, rg, nh, l);
    __syncthreads();   // all warps done reading Aex; safe to overwrite with C
#pragma unroll
    for (int mg = 0; mg < 2; mg++) {
        int rA = rg * 32 + mg * 16 + ar;
        int rB = rA + 8;
#pragma unroll
        for (int t = 0; t < 8; t++) {
            int c0 = nh * 64 + t * 8 + q * 2;
            sts64(sb + SM_AEX + (uint32_t)((rA * AROW + c0) * 4),
                  __float_as_uint(c[mg][t][0]), __float_as_uint(c[mg][t][1]));
            sts64(sb + SM_AEX + (uint32_t)((rB * AROW + c0) * 4),
                  __float_as_uint(c[mg][t][2]), __float_as_uint(c[mg][t][3]));
        }
    }
    __syncthreads();
    // coalesced scatter: 2048 float4s (64 rows x 32), 16 per thread
#pragma unroll
    for (int i = 0; i < 16; i++) {
        int f = i * NTE + tid;
        int row = f >> 5, c4 = f & 31;
        float4 v = *(const float4*)(smem + SM_AEX + (uint32_t)((row * AROW + c4 * 4) * 4));
        red4(&g_acc[hi_s[row] * D + c4 * 4], v.x, v.y, v.z, v.w);
    }
}

// ---------------------------------------------------------------------------
// FFMA node kernels (split so k_edge is launch #4 for ncu)
// ---------------------------------------------------------------------------
__device__ __forceinline__ void gemm_tile(const float* in_s, const float* __restrict__ W,
                                          float* wbuf, float acc[8][4], int e0, int c4, int tid) {
    const float4* Wg = reinterpret_cast<const float4*>(W);
    float4* wb = reinterpret_cast<float4*>(wbuf);
    for (int kb = 0; kb < D; kb += KC) {
        __syncthreads();
        wb[tid]      = Wg[kb * (D / 4) + tid];
        wb[tid + NT] = Wg[kb * (D / 4) + tid + NT];
        __syncthreads();
#pragma unroll
        for (int kk = 0; kk < KC; kk++) {
            float4 w = wb[kk * (D / 4) + c4];
#pragma unroll
            for (int i = 0; i < 8; i++) {
                float h = in_s[(e0 + i) * D + kb + kk];
                acc[i][0] = fmaf(h, w.x, acc[i][0]);
                acc[i][1] = fmaf(h, w.y, acc[i][1]);
                acc[i][2] = fmaf(h, w.z, acc[i][2]);
                acc[i][3] = fmaf(h, w.w, acc[i][3]);
            }
        }
    }
}

__device__ __forceinline__ void zero_acc(float acc[8][4]) {
#pragma unroll
    for (int i = 0; i < 8; i++)
#pragma unroll
        for (int j = 0; j < 4; j++) acc[i][j] = 0.f;
}

__device__ __forceinline__ void store_acc(float* io, const float acc[8][4], int e0, int c4) {
#pragma unroll
    for (int i = 0; i < 8; i++) {
        float4 v = make_float4(acc[i][0], acc[i][1], acc[i][2], acc[i][3]);
        *reinterpret_cast<float4*>(&io[(e0 + i) * D + c4 * 4]) = v;
    }
}

__device__ __forceinline__ void gn_rows(float* io, const float* __restrict__ g,
                                        const float* __restrict__ b, bool do_relu, int tid) {
    int lane = tid & 31, w = tid >> 5;
    for (int r = w; r < TR; r += 8) {
        float v[4], s = 0.f, sq = 0.f;
#pragma unroll
        for (int j = 0; j < 4; j++) {
            v[j] = io[r * D + lane + 32 * j];
            s += v[j]; sq += v[j] * v[j];
        }
#pragma unroll
        for (int o = 16; o > 0; o >>= 1) {
            s  += __shfl_xor_sync(0xffffffffu, s, o);
            sq += __shfl_xor_sync(0xffffffffu, sq, o);
        }
        float mean = s * (1.f / D);
        float var  = sq * (1.f / D) - mean * mean;
        float rstd = rsqrtf(var + EPS);
#pragma unroll
        for (int j = 0; j < 4; j++) {
            int c = lane + 32 * j;
            float x = (v[j] - mean) * rstd * g[c] + b[c];
            io[r * D + c] = do_relu ? fmaxf(x, 0.f) : x;
        }
    }
}

__global__ __launch_bounds__(NT) void k_nodes_a(const float* __restrict__ agts,
                                                const float* __restrict__ query_w,
                                                const float* __restrict__ query_g,
                                                const float* __restrict__ query_b,
                                                const float* __restrict__ ctx_w1,
                                                const float* __restrict__ agt_w) {
    __shared__ float io[TR * D];
    __shared__ float wbuf[KC * D];
    int tid = threadIdx.x;
    int task = blockIdx.x >> 8;
    int r0 = (blockIdx.x & 255) * TR;
    int lane = tid & 31, wid = tid >> 5;
    int c4 = lane, e0 = wid * 8;
    float acc[8][4];

    for (int idx = tid; idx < TR * D; idx += NT) io[idx] = agts[r0 * D + idx];

    if (task == 0) {
        zero_acc(acc);
        gemm_tile(io, query_w, wbuf, acc, e0, c4, tid);
        __syncthreads();
        store_acc(io, acc, e0, c4);
        __syncthreads();
        gn_rows(io, query_g, query_b, true, tid);
        __syncthreads();
        zero_acc(acc);
        gemm_tile(io, ctx_w1 + D * D, wbuf, acc, e0, c4, tid);
#pragma unroll
        for (int i = 0; i < 8; i++) {
            float4 v = make_float4(acc[i][0], acc[i][1], acc[i][2], acc[i][3]);
            *reinterpret_cast<float4*>(&g_qb[(r0 + e0 + i) * D + c4 * 4]) = v;
        }
    } else {
        zero_acc(acc);
        gemm_tile(io, agt_w, wbuf, acc, e0, c4, tid);
#pragma unroll
        for (int i = 0; i < 8; i++) {
            float4 v = make_float4(acc[i][0], acc[i][1], acc[i][2], acc[i][3]);
            *reinterpret_cast<float4*>(&g_acc[(r0 + e0 + i) * D + c4 * 4]) = v;
        }
    }
}

__global__ __launch_bounds__(NT) void k_nodes_b(const float* __restrict__ ctx,
                                                const float* __restrict__ ctx_w1) {
    __shared__ float io[TR * D];
    __shared__ float wbuf[KC * D];
    int tid = threadIdx.x;
    int r0 = blockIdx.x * TR;
    int lane = tid & 31, wid = tid >> 5;
    int c4 = lane, e0 = wid * 8;
    float acc[8][4];

    for (int idx = tid; idx < TR * D; idx += NT) io[idx] = ctx[r0 * D + idx];
    zero_acc(acc);
    gemm_tile(io, ctx_w1 + 2 * D * D, wbuf, acc, e0, c4, tid);
#pragma unroll
    for (int i = 0; i < 8; i++) {
        float4 v = make_float4(acc[i][0], acc[i][1], acc[i][2], acc[i][3]);
        *reinterpret_cast<float4*>(&g_ctxc[(r0 + e0 + i) * D + c4 * 4]) = v;
    }
}

__global__ __launch_bounds__(NT) void k_final(const float* __restrict__ agts,
                                              const float* __restrict__ norm_g,
                                              const float* __restrict__ norm_b,
                                              const float* __restrict__ lin_w,
                                              const float* __restrict__ lin_g,
                                              const float* __restrict__ lin_b,
                                              float* __restrict__ out) {
    __shared__ float io[TR * D];
    __shared__ float wbuf[KC * D];
    int tid = threadIdx.x;
    int r0 = blockIdx.x * TR;
    int lane = tid & 31, wid = tid >> 5;
    int c4 = lane, e0 = wid * 8;

    for (int idx = tid; idx < TR * D; idx += NT) io[idx] = g_acc[r0 * D + idx];
    __syncthreads();
    gn_rows(io, norm_g, norm_b, true, tid);
    __syncthreads();

    float acc[8][4];
    zero_acc(acc);
    gemm_tile(io, lin_w, wbuf, acc, e0, c4, tid);
    __syncthreads();
    store_acc(io, acc, e0, c4);
    __syncthreads();

    for (int r = wid; r < TR; r += 8) {
        float v[4], s = 0.f, sq = 0.f;
#pragma unroll
        for (int j = 0; j < 4; j++) {
            v[j] = io[r * D + lane + 32 * j];
            s += v[j]; sq += v[j] * v[j];
        }
#pragma unroll
        for (int o = 16; o > 0; o >>= 1) {
            s  += __shfl_xor_sync(0xffffffffu, s, o);
            sq += __shfl_xor_sync(0xffffffffu, sq, o);
        }
        float mean = s * (1.f / D);
        float var  = sq * (1.f / D) - mean * mean;
        float rstd = rsqrtf(var + EPS);
#pragma unroll
        for (int j = 0; j < 4; j++) {
            int c = lane + 32 * j;
            float x = (v[j] - mean) * rstd * lin_g[c] + lin_b[c];
            float res = agts[(r0 + r) * D + c];
            out[(r0 + r) * D + c] = fmaxf(x + res, 0.f);
        }
    }
}

// ---------------------------------------------------------------------------
extern "C" void kernel_launch(void* const* d_in, const int* in_sizes, int n_in,
                              void* d_out, int out_size) {
    const float* agts     = (const float*)d_in[0];
    const float* ctx      = (const float*)d_in[1];
    const float* agt_ctrs = (const float*)d_in[2];
    const float* ctx_ctrs = (const float*)d_in[3];
    const int*   hi       = (const int*)d_in[4];
    const int*   wi       = (const int*)d_in[5];
    const float* dist_w1  = (const float*)d_in[6];
    const float* dist_b1  = (const float*)d_in[7];
    const float* dist_w2  = (const float*)d_in[8];
    const float* dist_g2  = (const float*)d_in[9];
    const float* dist_b2  = (const float*)d_in[10];
    const float* query_w  = (const float*)d_in[11];
    const float* query_g  = (const float*)d_in[12];
    const float* query_b  = (const float*)d_in[13];
    const float* ctx_w1   = (const float*)d_in[14];
    const float* ctx_g1   = (const float*)d_in[15];
    const float* ctx_b1   = (const float*)d_in[16];
    const float* ctx_w2   = (const float*)d_in[17];
    const float* agt_w    = (const float*)d_in[18];
    const float* norm_g   = (const float*)d_in[19];
    const float* norm_b   = (const float*)d_in[20];
    const float* lin_w    = (const float*)d_in[21];
    const float* lin_g    = (const float*)d_in[22];
    const float* lin_b    = (const float*)d_in[23];
    float* out = (float*)d_out;

    cudaFuncSetAttribute(k_edge_mma, cudaFuncAttributeMaxDynamicSharedMemorySize, SMEM_EDGE);

    k_prep<<<dim3(64, 3), 256>>>(dist_w2, ctx_w1, ctx_w2);                 // launch 1
    k_nodes_a<<<512, NT>>>(agts, query_w, query_g, query_b, ctx_w1, agt_w);// launch 2
    k_nodes_b<<<256, NT>>>(ctx, ctx_w1);                                   // launch 3
    k_edge_mma<<<NE / TRE, NTE, SMEM_EDGE>>>(agt_ctrs, ctx_ctrs, hi, wi,   // launch 4 (ncu)
                                             dist_w1, dist_b1,
                                             dist_g2, dist_b2,
                                             ctx_g1, ctx_b1);
    k_final<<<NA / TR, NT>>>(agts, norm_g, norm_b, lin_w, lin_g, lin_b, out);
}

// round 12
// speedup vs baseline: 1.0852x; 1.0852x over previous
#include <cuda_runtime.h>
#include <cuda_bf16.h>
#include <cstdint>

#define D     128
#define NA    16384
#define NC    16384
#define NE    524288
#define TR    64
#define NT    256
#define KC    16
#define TRE   64      // edges per block (4 row-groups x 2 col-halves = 8 warps)
#define EPS   1e-5f
#define AROW  132     // floats per Aex row (bank-conflict-free stride)

// ---------------------------------------------------------------------------
// device scratch (no allocation)
// ---------------------------------------------------------------------------
__device__ __align__(16) float g_qb[NA * D];      // relu(GN(agts@query_w)) @ ctx_w1[128:256]
__device__ __align__(16) float g_ctxc[NC * D];    // ctx @ ctx_w1[256:384]
__device__ __align__(16) float g_acc[NA * D];     // agts@agt_w + scattered edge output
__device__ __align__(16) uint32_t g_wt[3 * 16384];// tf32 W images, FRAGMENT-ORDERED

// ---------------------------------------------------------------------------
// helpers
// ---------------------------------------------------------------------------
__device__ __forceinline__ uint32_t smem_u32(const void* p) {
    uint32_t a;
    asm("{ .reg .u64 t; cvta.to.shared.u64 t, %1; cvt.u32.u64 %0, t; }" : "=r"(a) : "l"(p));
    return a;
}

__device__ __forceinline__ uint32_t f2tf(float x) {
    uint32_t u;
    asm("cvt.rna.tf32.f32 %0, %1;" : "=r"(u) : "f"(x));
    return u;
}

__device__ __forceinline__ void mma_tf32(float c[4], const uint32_t a[4], uint32_t b0, uint32_t b1) {
    asm volatile(
        "mma.sync.aligned.m16n8k8.row.col.f32.tf32.tf32.f32 "
        "{%0,%1,%2,%3}, {%4,%5,%6,%7}, {%8,%9}, {%0,%1,%2,%3};"
        : "+f"(c[0]), "+f"(c[1]), "+f"(c[2]), "+f"(c[3])
        : "r"(a[0]), "r"(a[1]), "r"(a[2]), "r"(a[3]), "r"(b0), "r"(b1));
}

__device__ __forceinline__ uint32_t lds32(uint32_t a) {
    uint32_t v;
    asm volatile("ld.shared.b32 %0, [%1];" : "=r"(v) : "r"(a));
    return v;
}
__device__ __forceinline__ float lds32f(uint32_t a) {
    float v;
    asm volatile("ld.shared.f32 %0, [%1];" : "=f"(v) : "r"(a));
    return v;
}
__device__ __forceinline__ void sts64(uint32_t a, uint32_t x, uint32_t y) {
    asm volatile("st.shared.v2.b32 [%0], {%1, %2};" :: "r"(a), "r"(x), "r"(y) : "memory");
}

__device__ __forceinline__ void red4(float* p, float a, float b, float c, float d) {
    asm volatile("red.global.add.v4.f32 [%0], {%1,%2,%3,%4};"
                 :: "l"(p), "f"(a), "f"(b), "f"(c), "f"(d) : "memory");
}

// ---------------------------------------------------------------------------
// k_edge smem map (bytes): NO W buffer — B comes from L1 via LDG
// ---------------------------------------------------------------------------
#define SM_AEX    0        /* 64 rows x AROW floats = 33792B */
#define SM_STATS  33792    /* 256 floats */
#define SM_GB     34816    /* 512 floats: g2,b2,cg1,cb1 */
#define SM_HIS    36864
#define SM_WIS    37120
#define SM_D2     37376
#define SMEM_EDGE 37888

// Fragment-ordered W image: float index = nh*8192 + kc*512 + j*128 + lane*4 + e
//   lane = bn*4 + bk;  j = khalf*2 + (p>>2);  e = p&3
//   where k = kc*8 + khalf*4 + bk,  n = nh*64 + p*8 + bn
__global__ void k_prep(const float* __restrict__ w0, const float* __restrict__ w1,
                       const float* __restrict__ w2) {
    int m = blockIdx.y;
    const float* src = (m == 0) ? w0 : (m == 1 ? w1 : w2);
    int idx = blockIdx.x * 256 + threadIdx.x;    // k*128 + n
    int k = idx >> 7, n = idx & 127;
    int kc = k >> 3, kloc = k & 7, bk = kloc & 3, khalf = kloc >> 2;
    int nh = n >> 6, p = (n >> 3) & 7, bn = n & 7;
    int j = khalf * 2 + (p >> 2);
    int e = p & 3;
    int l = bn * 4 + bk;
    int dest = nh * 8192 + kc * 512 + j * 128 + l * 4 + e;
    g_wt[m * 16384 + dest] = f2tf(src[idx]);
}

// C[8 tiles][4] += A[16 rows in smem] @ W[B frags via LDG from L1]
// warp rows rg*16..+15, cols nh*64..+63
__device__ __forceinline__ void mma_stage(float c[8][4], uint32_t sb,
                                          const uint4* __restrict__ wg,
                                          int rg, int nh, int l) {
    const int ar = l >> 2, ak = l & 3;
    const uint32_t abase = sb + SM_AEX + (uint32_t)(((rg * 16 + ar) * AROW + ak) * 4);
    const uint4* bbase = wg + nh * 2048 + l;   // uint4 idx: nh*2048 + kc*128 + j*32 + l
#pragma unroll
    for (int kc = 0; kc < 16; kc++) {
        uint4 B0 = __ldg(bbase + kc * 128);        // first-op  p0..3
        uint4 B1 = __ldg(bbase + kc * 128 + 32);   // first-op  p4..7
        uint4 B2 = __ldg(bbase + kc * 128 + 64);   // second-op p0..3
        uint4 B3 = __ldg(bbase + kc * 128 + 96);   // second-op p4..7
        uint32_t a[4];
        uint32_t aa = abase + (uint32_t)(kc * 32);
        a[0] = lds32(aa);
        a[2] = lds32(aa + 16);
        a[1] = lds32(aa + 8 * AROW * 4);
        a[3] = lds32(aa + 8 * AROW * 4 + 16);
        mma_tf32(c[0], a, B0.x, B2.x);
        mma_tf32(c[1], a, B0.y, B2.y);
        mma_tf32(c[2], a, B0.z, B2.z);
        mma_tf32(c[3], a, B0.w, B2.w);
        mma_tf32(c[4], a, B1.x, B3.x);
        mma_tf32(c[5], a, B1.y, B3.y);
        mma_tf32(c[6], a, B1.z, B3.z);
        mma_tf32(c[7], a, B1.w, B3.w);
    }
}

// GN(+relu) epilogue: stats -> barrier -> normalize (gamma/beta from smem stash)
// -> Aex(tf32) -> barrier
template <bool GATHER>
__device__ __forceinline__ void ep_gn(float c[8][4],
                                      uint32_t gboff,   // smem byte offset of gamma (beta at +512)
                                      uint32_t sb, char* smem,
                                      const int* hi_s, const int* wi_s,
                                      const float2* pq, const float2* pc,
                                      int rg, int nh, int l) {
    const int q = l & 3;
    const int rA = rg * 16 + (l >> 2);
    const int rB = rA + 8;
    const int cb = nh * 64;

    if (GATHER) {
        // rA terms were prefetched into pq/pc before the mma; load rB fresh
        const float* qB = g_qb   + hi_s[rB] * D + cb;
        const float* cB = g_ctxc + wi_s[rB] * D + cb;
#pragma unroll
        for (int t = 0; t < 8; t++) {
            float2 b1 = __ldg((const float2*)(qB + t * 8) + q);
            float2 b2 = __ldg((const float2*)(cB + t * 8) + q);
            c[t][0] += pq[t].x + pc[t].x;
            c[t][1] += pq[t].y + pc[t].y;
            c[t][2] += b1.x + b2.x;
            c[t][3] += b1.y + b2.y;
        }
    }
    float sA = 0.f, qsA = 0.f, sB = 0.f, qsB = 0.f;
#pragma unroll
    for (int t = 0; t < 8; t++) {
        sA += c[t][0] + c[t][1];
        qsA = fmaf(c[t][0], c[t][0], fmaf(c[t][1], c[t][1], qsA));
        sB += c[t][2] + c[t][3];
        qsB = fmaf(c[t][2], c[t][2], fmaf(c[t][3], c[t][3], qsB));
    }
    sA  += __shfl_xor_sync(~0u, sA, 1);  sA  += __shfl_xor_sync(~0u, sA, 2);
    qsA += __shfl_xor_sync(~0u, qsA, 1); qsA += __shfl_xor_sync(~0u, qsA, 2);
    sB  += __shfl_xor_sync(~0u, sB, 1);  sB  += __shfl_xor_sync(~0u, sB, 2);
    qsB += __shfl_xor_sync(~0u, qsB, 1); qsB += __shfl_xor_sync(~0u, qsB, 2);

    float* st = (float*)(smem + SM_STATS);   // [half][sum(64) | sq(64)]
    if (q == 0) {
        st[nh * 128 + rA]      = sA;  st[nh * 128 + 64 + rA] = qsA;
        st[nh * 128 + rB]      = sB;  st[nh * 128 + 64 + rB] = qsB;
    }
    __syncthreads();   // stats visible; all Aex reads of this stage done

    float S   = st[rA] + st[128 + rA];
    float SQ  = st[64 + rA] + st[192 + rA];
    float Sb  = st[rB] + st[128 + rB];
    float SQb = st[64 + rB] + st[192 + rB];
    float mA = S  * (1.f / 128.f), vA = SQ  * (1.f / 128.f) - mA * mA, rsA = rsqrtf(vA + EPS);
    float mB = Sb * (1.f / 128.f), vB = SQb * (1.f / 128.f) - mB * mB, rsB = rsqrtf(vB + EPS);

#pragma unroll
    for (int t = 0; t < 8; t++) {
        int c0 = cb + t * 8 + q * 2;
        float g0 = lds32f(sb + gboff + (uint32_t)(c0 * 4));
        float g1 = lds32f(sb + gboff + (uint32_t)(c0 * 4) + 4);
        float b0 = lds32f(sb + gboff + 512u + (uint32_t)(c0 * 4));
        float b1 = lds32f(sb + gboff + 512u + (uint32_t)(c0 * 4) + 4);
        float xA0 = fmaxf(fmaf((c[t][0] - mA) * rsA, g0, b0), 0.f);
        float xA1 = fmaxf(fmaf((c[t][1] - mA) * rsA, g1, b1), 0.f);
        float xB0 = fmaxf(fmaf((c[t][2] - mB) * rsB, g0, b0), 0.f);
        float xB1 = fmaxf(fmaf((c[t][3] - mB) * rsB, g1, b1), 0.f);
        sts64(sb + SM_AEX + (uint32_t)((rA * AROW + c0) * 4), f2tf(xA0), f2tf(xA1));
        sts64(sb + SM_AEX + (uint32_t)((rB * AROW + c0) * 4), f2tf(xB0), f2tf(xB1));
    }
    __syncthreads();   // Aex visible
}

__global__ __launch_bounds__(256, 2) void k_edge_mma(
    const float* __restrict__ agt_ctrs, const float* __restrict__ ctx_ctrs,
    const int* __restrict__ hi, const int* __restrict__ wi,
    const float* __restrict__ dist_w1, const float* __restrict__ dist_b1,
    const float* __restrict__ dist_g2, const float* __restrict__ dist_b2,
    const float* __restrict__ ctx_g1, const float* __restrict__ ctx_b1) {
    extern __shared__ char smem[];
    const uint32_t sb = smem_u32(smem);
    const int tid = threadIdx.x;
    const int w = tid >> 5, l = tid & 31, q = l & 3;
    const int rg = w >> 1, nh = w & 1;         // row group 0-3, col half 0-1
    const int rA = rg * 16 + (l >> 2);
    const int rB = rA + 8;

    int* hi_s = (int*)(smem + SM_HIS);
    int* wi_s = (int*)(smem + SM_WIS);
    float2* d2s = (float2*)(smem + SM_D2);
    float* gbs = (float*)(smem + SM_GB);
    const int e0 = blockIdx.x * TRE;
    if (tid < TRE) {
        int h = hi[e0 + tid], ww = wi[e0 + tid];
        hi_s[tid] = h; wi_s[tid] = ww;
        float2 ac = ((const float2*)agt_ctrs)[h];
        float2 cc = ((const float2*)ctx_ctrs)[ww];
        d2s[tid] = make_float2(ac.x - cc.x, ac.y - cc.y);
    }
    // gamma/beta stash: [0:128) g2 [128:256) b2 [256:384) cg1 [384:512) cb1
    gbs[tid]       = (tid < 128) ? __ldg(dist_g2 + tid) : __ldg(dist_b2 + tid - 128);
    gbs[256 + tid] = (tid < 128) ? __ldg(ctx_g1 + tid)  : __ldg(ctx_b1 + tid - 128);
    __syncthreads();                           // ids/d2/gb visible

    // initial A = relu(d2 @ dist_w1 + b1) -> Aex as tf32
    for (int idx = tid; idx < TRE * D; idx += 256) {
        int row = idx >> 7, col = idx & 127;
        float2 dd = d2s[row];
        float x = fmaxf(fmaf(dd.x, __ldg(dist_w1 + col),
                     fmaf(dd.y, __ldg(dist_w1 + D + col), __ldg(dist_b1 + col))), 0.f);
        *(uint32_t*)(smem + SM_AEX + (row * AROW + col) * 4) = f2tf(x);
    }
    __syncthreads();                           // Aex visible

    float c[8][4];
    // ---- stage 1: @ dist_w2, GN(dist_g2,b2)+relu ----
#pragma unroll
    for (int t = 0; t < 8; t++) { c[t][0] = c[t][1] = c[t][2] = c[t][3] = 0.f; }
    mma_stage(c, sb, (const uint4*)g_wt, rg, nh, l);
    ep_gn<false>(c, SM_GB, sb, smem, hi_s, wi_s, nullptr, nullptr, rg, nh, l);

    // ---- stage 2: @ ctx_w1[0:128] + qb[hi] + ctxc[wi], GN(ctx_g1,b1)+relu ----
    float2 pq[8], pc[8];
    {
        const int cb = nh * 64;
        const float* qA = g_qb   + hi_s[rA] * D + cb;
        const float* cA = g_ctxc + wi_s[rA] * D + cb;
#pragma unroll
        for (int t = 0; t < 8; t++) {
            pq[t] = __ldg((const float2*)(qA + t * 8) + q);
            pc[t] = __ldg((const float2*)(cA + t * 8) + q);
        }
    }
#pragma unroll
    for (int t = 0; t < 8; t++) { c[t][0] = c[t][1] = c[t][2] = c[t][3] = 0.f; }
    mma_stage(c, sb, (const uint4*)(g_wt + 16384), rg, nh, l);
    ep_gn<true>(c, SM_GB + 1024, sb, smem, hi_s, wi_s, pq, pc, rg, nh, l);

    // ---- stage 3: @ ctx_w2, scatter-add ----
#pragma unroll
    for (int t = 0; t < 8; t++) { c[t][0] = c[t][1] = c[t][2] = c[t][3] = 0.f; }
    mma_stage(c, sb, (const uint4*)(g_wt + 32768), rg, nh, l);
    {
        float* baseA = g_acc + hi_s[rA] * D + nh * 64;
        float* baseB = g_acc + hi_s[rB] * D + nh * 64;
        const bool even = (q & 1) == 0;
#pragma unroll
        for (int t = 0; t < 8; t++) {
            float x0 = __shfl_xor_sync(~0u, c[t][0], 1);
            float x1 = __shfl_xor_sync(~0u, c[t][1], 1);
            float x2 = __shfl_xor_sync(~0u, c[t][2], 1);
            float x3 = __shfl_xor_sync(~0u, c[t][3], 1);
            if (even) red4(baseA + t * 8 + q * 2,       c[t][0], c[t][1], x0, x1);
            else      red4(baseB + t * 8 + (q - 1) * 2, x2, x3, c[t][2], c[t][3]);
        }
    }
}

// ---------------------------------------------------------------------------
// FFMA node kernels (split so k_edge is launch #4 for ncu)
// ---------------------------------------------------------------------------
__device__ __forceinline__ void gemm_tile(const float* in_s, const float* __restrict__ W,
                                          float* wbuf, float acc[8][4], int e0, int c4, int tid) {
    const float4* Wg = reinterpret_cast<const float4*>(W);
    float4* wb = reinterpret_cast<float4*>(wbuf);
    for (int kb = 0; kb < D; kb += KC) {
        __syncthreads();
        wb[tid]      = Wg[kb * (D / 4) + tid];
        wb[tid + NT] = Wg[kb * (D / 4) + tid + NT];
        __syncthreads();
#pragma unroll
        for (int kk = 0; kk < KC; kk++) {
            float4 w = wb[kk * (D / 4) + c4];
#pragma unroll
            for (int i = 0; i < 8; i++) {
                float h = in_s[(e0 + i) * D + kb + kk];
                acc[i][0] = fmaf(h, w.x, acc[i][0]);
                acc[i][1] = fmaf(h, w.y, acc[i][1]);
                acc[i][2] = fmaf(h, w.z, acc[i][2]);
                acc[i][3] = fmaf(h, w.w, acc[i][3]);
            }
        }
    }
}

__device__ __forceinline__ void zero_acc(float acc[8][4]) {
#pragma unroll
    for (int i = 0; i < 8; i++)
#pragma unroll
        for (int j = 0; j < 4; j++) acc[i][j] = 0.f;
}

__device__ __forceinline__ void store_acc(float* io, const float acc[8][4], int e0, int c4) {
#pragma unroll
    for (int i = 0; i < 8; i++) {
        float4 v = make_float4(acc[i][0], acc[i][1], acc[i][2], acc[i][3]);
        *reinterpret_cast<float4*>(&io[(e0 + i) * D + c4 * 4]) = v;
    }
}

__device__ __forceinline__ void gn_rows(float* io, const float* __restrict__ g,
                                        const float* __restrict__ b, bool do_relu, int tid) {
    int lane = tid & 31, w = tid >> 5;
    for (int r = w; r < TR; r += 8) {
        float v[4], s = 0.f, sq = 0.f;
#pragma unroll
        for (int j = 0; j < 4; j++) {
            v[j] = io[r * D + lane + 32 * j];
            s += v[j]; sq += v[j] * v[j];
        }
#pragma unroll
        for (int o = 16; o > 0; o >>= 1) {
            s  += __shfl_xor_sync(0xffffffffu, s, o);
            sq += __shfl_xor_sync(0xffffffffu, sq, o);
        }
        float mean = s * (1.f / D);
        float var  = sq * (1.f / D) - mean * mean;
        float rstd = rsqrtf(var + EPS);
#pragma unroll
        for (int j = 0; j < 4; j++) {
            int c = lane + 32 * j;
            float x = (v[j] - mean) * rstd * g[c] + b[c];
            io[r * D + c] = do_relu ? fmaxf(x, 0.f) : x;
        }
    }
}

__global__ __launch_bounds__(NT) void k_nodes_a(const float* __restrict__ agts,
                                                const float* __restrict__ query_w,
                                                const float* __restrict__ query_g,
                                                const float* __restrict__ query_b,
                                                const float* __restrict__ ctx_w1,
                                                const float* __restrict__ agt_w) {
    __shared__ float io[TR * D];
    __shared__ float wbuf[KC * D];
    int tid = threadIdx.x;
    int task = blockIdx.x >> 8;
    int r0 = (blockIdx.x & 255) * TR;
    int lane = tid & 31, wid = tid >> 5;
    int c4 = lane, e0 = wid * 8;
    float acc[8][4];

    for (int idx = tid; idx < TR * D; idx += NT) io[idx] = agts[r0 * D + idx];

    if (task == 0) {
        zero_acc(acc);
        gemm_tile(io, query_w, wbuf, acc, e0, c4, tid);
        __syncthreads();
        store_acc(io, acc, e0, c4);
        __syncthreads();
        gn_rows(io, query_g, query_b, true, tid);
        __syncthreads();
        zero_acc(acc);
        gemm_tile(io, ctx_w1 + D * D, wbuf, acc, e0, c4, tid);
#pragma unroll
        for (int i = 0; i < 8; i++) {
            float4 v = make_float4(acc[i][0], acc[i][1], acc[i][2], acc[i][3]);
            *reinterpret_cast<float4*>(&g_qb[(r0 + e0 + i) * D + c4 * 4]) = v;
        }
    } else {
        zero_acc(acc);
        gemm_tile(io, agt_w, wbuf, acc, e0, c4, tid);
#pragma unroll
        for (int i = 0; i < 8; i++) {
            float4 v = make_float4(acc[i][0], acc[i][1], acc[i][2], acc[i][3]);
            *reinterpret_cast<float4*>(&g_acc[(r0 + e0 + i) * D + c4 * 4]) = v;
        }
    }
}

__global__ __launch_bounds__(NT) void k_nodes_b(const float* __restrict__ ctx,
                                                const float* __restrict__ ctx_w1) {
    __shared__ float io[TR * D];
    __shared__ float wbuf[KC * D];
    int tid = threadIdx.x;
    int r0 = blockIdx.x * TR;
    int lane = tid & 31, wid = tid >> 5;
    int c4 = lane, e0 = wid * 8;
    float acc[8][4];

    for (int idx = tid; idx < TR * D; idx += NT) io[idx] = ctx[r0 * D + idx];
    zero_acc(acc);
    gemm_tile(io, ctx_w1 + 2 * D * D, wbuf, acc, e0, c4, tid);
#pragma unroll
    for (int i = 0; i < 8; i++) {
        float4 v = make_float4(acc[i][0], acc[i][1], acc[i][2], acc[i][3]);
        *reinterpret_cast<float4*>(&g_ctxc[(r0 + e0 + i) * D + c4 * 4]) = v;
    }
}

__global__ __launch_bounds__(NT) void k_final(const float* __restrict__ agts,
                                              const float* __restrict__ norm_g,
                                              const float* __restrict__ norm_b,
                                              const float* __restrict__ lin_w,
                                              const float* __restrict__ lin_g,
                                              const float* __restrict__ lin_b,
                                              float* __restrict__ out) {
    __shared__ float io[TR * D];
    __shared__ float wbuf[KC * D];
    int tid = threadIdx.x;
    int r0 = blockIdx.x * TR;
    int lane = tid & 31, wid = tid >> 5;
    int c4 = lane, e0 = wid * 8;

    for (int idx = tid; idx < TR * D; idx += NT) io[idx] = g_acc[r0 * D + idx];
    __syncthreads();
    gn_rows(io, norm_g, norm_b, true, tid);
    __syncthreads();

    float acc[8][4];
    zero_acc(acc);
    gemm_tile(io, lin_w, wbuf, acc, e0, c4, tid);
    __syncthreads();
    store_acc(io, acc, e0, c4);
    __syncthreads();

    for (int r = wid; r < TR; r += 8) {
        float v[4], s = 0.f, sq = 0.f;
#pragma unroll
        for (int j = 0; j < 4; j++) {
            v[j] = io[r * D + lane + 32 * j];
            s += v[j]; sq += v[j] * v[j];
        }
#pragma unroll
        for (int o = 16; o > 0; o >>= 1) {
            s  += __shfl_xor_sync(0xffffffffu, s, o);
            sq += __shfl_xor_sync(0xffffffffu, sq, o);
        }
        float mean = s * (1.f / D);
        float var  = sq * (1.f / D) - mean * mean;
        float rstd = rsqrtf(var + EPS);
#pragma unroll
        for (int j = 0; j < 4; j++) {
            int c = lane + 32 * j;
            float x = (v[j] - mean) * rstd * lin_g[c] + lin_b[c];
            float res = agts[(r0 + r) * D + c];
            out[(r0 + r) * D + c] = fmaxf(x + res, 0.f);
        }
    }
}

// ---------------------------------------------------------------------------
extern "C" void kernel_launch(void* const* d_in, const int* in_sizes, int n_in,
                              void* d_out, int out_size) {
    const float* agts     = (const float*)d_in[0];
    const float* ctx      = (const float*)d_in[1];
    const float* agt_ctrs = (const float*)d_in[2];
    const float* ctx_ctrs = (const float*)d_in[3];
    const int*   hi       = (const int*)d_in[4];
    const int*   wi       = (const int*)d_in[5];
    const float* dist_w1  = (const float*)d_in[6];
    const float* dist_b1  = (const float*)d_in[7];
    const float* dist_w2  = (const float*)d_in[8];
    const float* dist_g2  = (const float*)d_in[9];
    const float* dist_b2  = (const float*)d_in[10];
    const float* query_w  = (const float*)d_in[11];
    const float* query_g  = (const float*)d_in[12];
    const float* query_b  = (const float*)d_in[13];
    const float* ctx_w1   = (const float*)d_in[14];
    const float* ctx_g1   = (const float*)d_in[15];
    const float* ctx_b1   = (const float*)d_in[16];
    const float* ctx_w2   = (const float*)d_in[17];
    const float* agt_w    = (const float*)d_in[18];
    const float* norm_g   = (const float*)d_in[19];
    const float* norm_b   = (const float*)d_in[20];
    const float* lin_w    = (const float*)d_in[21];
    const float* lin_g    = (const float*)d_in[22];
    const float* lin_b    = (const float*)d_in[23];
    float* out = (float*)d_out;

    cudaFuncSetAttribute(k_edge_mma, cudaFuncAttributeMaxDynamicSharedMemorySize, SMEM_EDGE);

    k_prep<<<dim3(64, 3), 256>>>(dist_w2, ctx_w1, ctx_w2);                 // launch 1
    k_nodes_a<<<512, NT>>>(agts, query_w, query_g, query_b, ctx_w1, agt_w);// launch 2
    k_nodes_b<<<256, NT>>>(ctx, ctx_w1);                                   // launch 3
    k_edge_mma<<<NE / TRE, 256, SMEM_EDGE>>>(agt_ctrs, ctx_ctrs, hi, wi,   // launch 4 (ncu)
                                             dist_w1, dist_b1,
                                             dist_g2, dist_b2,
                                             ctx_g1, ctx_b1);
    k_final<<<NA / TR, NT>>>(agts, norm_g, norm_b, lin_w, lin_g, lin_b, out);
}

// round 13
// speedup vs baseline: 1.2453x; 1.1475x over previous
#include <cuda_runtime.h>
#include <cuda_bf16.h>
#include <cstdint>

#define D     128
#define NA    16384
#define NC    16384
#define NE    524288
#define TR    64
#define NT    256
#define KC    16
#define TRE   128     // edges per block (4 row-groups x 32 rows, 2 col-halves; 8 warps)
#define EPS   1e-5f
#define AROW  132     // floats per Aex row (bank-conflict-free stride)

// ---------------------------------------------------------------------------
// device scratch (no allocation)
// ---------------------------------------------------------------------------
__device__ __align__(16) float g_qb[NA * D];      // relu(GN(agts@query_w)) @ ctx_w1[128:256]
__device__ __align__(16) float g_ctxc[NC * D];    // ctx @ ctx_w1[256:384]
__device__ __align__(16) float g_acc[NA * D];     // agts@agt_w + scattered edge output
__device__ __align__(16) uint32_t g_wt[3 * 16384];// tf32 W images, FRAGMENT-ORDERED

// ---------------------------------------------------------------------------
// helpers
// ---------------------------------------------------------------------------
__device__ __forceinline__ uint32_t smem_u32(const void* p) {
    uint32_t a;
    asm("{ .reg .u64 t; cvta.to.shared.u64 t, %1; cvt.u32.u64 %0, t; }" : "=r"(a) : "l"(p));
    return a;
}

__device__ __forceinline__ uint32_t f2tf(float x) {
    uint32_t u;
    asm("cvt.rna.tf32.f32 %0, %1;" : "=r"(u) : "f"(x));
    return u;
}

__device__ __forceinline__ void mma_tf32(float c[4], const uint32_t a[4], uint32_t b0, uint32_t b1) {
    asm volatile(
        "mma.sync.aligned.m16n8k8.row.col.f32.tf32.tf32.f32 "
        "{%0,%1,%2,%3}, {%4,%5,%6,%7}, {%8,%9}, {%0,%1,%2,%3};"
        : "+f"(c[0]), "+f"(c[1]), "+f"(c[2]), "+f"(c[3])
        : "r"(a[0]), "r"(a[1]), "r"(a[2]), "r"(a[3]), "r"(b0), "r"(b1));
}

__device__ __forceinline__ uint32_t lds32(uint32_t a) {
    uint32_t v;
    asm volatile("ld.shared.b32 %0, [%1];" : "=r"(v) : "r"(a));
    return v;
}
__device__ __forceinline__ float lds32f(uint32_t a) {
    float v;
    asm volatile("ld.shared.f32 %0, [%1];" : "=f"(v) : "r"(a));
    return v;
}
__device__ __forceinline__ void sts64(uint32_t a, uint32_t x, uint32_t y) {
    asm volatile("st.shared.v2.b32 [%0], {%1, %2};" :: "r"(a), "r"(x), "r"(y) : "memory");
}

__device__ __forceinline__ void red4(float* p, float a, float b, float c, float d) {
    asm volatile("red.global.add.v4.f32 [%0], {%1,%2,%3,%4};"
                 :: "l"(p), "f"(a), "f"(b), "f"(c), "f"(d) : "memory");
}

// ---------------------------------------------------------------------------
// k_edge smem map (bytes): NO W buffer — B comes from L1 via LDG
// ---------------------------------------------------------------------------
#define SM_AEX    0        /* 128 rows x AROW floats = 67584B */
#define SM_STATS  67584    /* 512 floats */
#define SM_GB     69632    /* 512 floats: g2,b2,cg1,cb1 */
#define SM_HIS    71680
#define SM_WIS    72192
#define SM_D2     72704
#define SMEM_EDGE 73728

// Fragment-ordered W image: float index = nh*8192 + kc*512 + j*128 + lane*4 + e
//   lane = bn*4 + bk;  j = khalf*2 + (p>>2);  e = p&3
//   where k = kc*8 + khalf*4 + bk,  n = nh*64 + p*8 + bn
__global__ void k_prep(const float* __restrict__ w0, const float* __restrict__ w1,
                       const float* __restrict__ w2) {
    int m = blockIdx.y;
    const float* src = (m == 0) ? w0 : (m == 1 ? w1 : w2);
    int idx = blockIdx.x * 256 + threadIdx.x;    // k*128 + n
    int k = idx >> 7, n = idx & 127;
    int kc = k >> 3, kloc = k & 7, bk = kloc & 3, khalf = kloc >> 2;
    int nh = n >> 6, p = (n >> 3) & 7, bn = n & 7;
    int j = khalf * 2 + (p >> 2);
    int e = p & 3;
    int l = bn * 4 + bk;
    int dest = nh * 8192 + kc * 512 + j * 128 + l * 4 + e;
    g_wt[m * 16384 + dest] = f2tf(src[idx]);
}

// C[2 mg][8 tiles][4] += A[32 rows in smem] @ W[B frags via LDG from L1]
// warp rows rg*32..+31, cols nh*64..+63.
// Per kc: 2 half-steps of (2x LDG.128 + 8 mma) keep B register lifetime short.
__device__ __forceinline__ void mma_stage(float c[2][8][4], uint32_t sb,
                                          const uint4* __restrict__ wg,
                                          int rg, int nh, int l) {
    const int ar = l >> 2, ak = l & 3;
    const uint32_t a0base = sb + SM_AEX + (uint32_t)(((rg * 32 + ar) * AROW + ak) * 4);
    const uint4* bbase = wg + nh * 2048 + l;   // uint4 idx: nh*2048 + kc*128 + j*32 + l
#pragma unroll
    for (int kc = 0; kc < 16; kc++) {
        uint32_t a[2][4];
#pragma unroll
        for (int mg = 0; mg < 2; mg++) {
            uint32_t aa = a0base + (uint32_t)(mg * 16 * AROW * 4 + kc * 32);
            a[mg][0] = lds32(aa);
            a[mg][2] = lds32(aa + 16);
            a[mg][1] = lds32(aa + 8 * AROW * 4);
            a[mg][3] = lds32(aa + 8 * AROW * 4 + 16);
        }
        {   // p = 0..3
            uint4 B0 = __ldg(bbase + kc * 128);        // first-op  p0..3
            uint4 B2 = __ldg(bbase + kc * 128 + 64);   // second-op p0..3
            mma_tf32(c[0][0], a[0], B0.x, B2.x);
            mma_tf32(c[0][1], a[0], B0.y, B2.y);
            mma_tf32(c[0][2], a[0], B0.z, B2.z);
            mma_tf32(c[0][3], a[0], B0.w, B2.w);
            mma_tf32(c[1][0], a[1], B0.x, B2.x);
            mma_tf32(c[1][1], a[1], B0.y, B2.y);
            mma_tf32(c[1][2], a[1], B0.z, B2.z);
            mma_tf32(c[1][3], a[1], B0.w, B2.w);
        }
        {   // p = 4..7
            uint4 B1 = __ldg(bbase + kc * 128 + 32);   // first-op  p4..7
            uint4 B3 = __ldg(bbase + kc * 128 + 96);   // second-op p4..7
            mma_tf32(c[0][4], a[0], B1.x, B3.x);
            mma_tf32(c[0][5], a[0], B1.y, B3.y);
            mma_tf32(c[0][6], a[0], B1.z, B3.z);
            mma_tf32(c[0][7], a[0], B1.w, B3.w);
            mma_tf32(c[1][4], a[1], B1.x, B3.x);
            mma_tf32(c[1][5], a[1], B1.y, B3.y);
            mma_tf32(c[1][6], a[1], B1.z, B3.z);
            mma_tf32(c[1][7], a[1], B1.w, B3.w);
        }
    }
}

// GN(+relu) epilogue: (gather) -> stats -> barrier -> normalize (gb from smem)
// -> Aex(tf32) -> barrier
template <bool GATHER>
__device__ __forceinline__ void ep_gn(float c[2][8][4],
                                      uint32_t gboff,   // smem byte offset of gamma (beta at +512)
                                      uint32_t sb, char* smem,
                                      const int* hi_s, const int* wi_s,
                                      int rg, int nh, int l) {
    const int q = l & 3;
    const int ar = l >> 2;
    const int cb = nh * 64;

    if (GATHER) {
#pragma unroll
        for (int mg = 0; mg < 2; mg++) {
            int r0 = rg * 32 + mg * 16 + ar;
            const float* qA = g_qb   + hi_s[r0] * D + cb;
            const float* cA = g_ctxc + wi_s[r0] * D + cb;
            const float* qB = g_qb   + hi_s[r0 + 8] * D + cb;
            const float* cB = g_ctxc + wi_s[r0 + 8] * D + cb;
#pragma unroll
            for (int t = 0; t < 8; t++) {
                float2 a1 = __ldg((const float2*)(qA + t * 8) + q);
                float2 a2 = __ldg((const float2*)(cA + t * 8) + q);
                float2 b1 = __ldg((const float2*)(qB + t * 8) + q);
                float2 b2 = __ldg((const float2*)(cB + t * 8) + q);
                c[mg][t][0] += a1.x + a2.x;  c[mg][t][1] += a1.y + a2.y;
                c[mg][t][2] += b1.x + b2.x;  c[mg][t][3] += b1.y + b2.y;
            }
        }
    }
    float s[4] = {0.f, 0.f, 0.f, 0.f}, qs[4] = {0.f, 0.f, 0.f, 0.f};
#pragma unroll
    for (int mg = 0; mg < 2; mg++)
#pragma unroll
        for (int t = 0; t < 8; t++) {
            s[mg * 2]     += c[mg][t][0] + c[mg][t][1];
            qs[mg * 2]     = fmaf(c[mg][t][0], c[mg][t][0], fmaf(c[mg][t][1], c[mg][t][1], qs[mg * 2]));
            s[mg * 2 + 1] += c[mg][t][2] + c[mg][t][3];
            qs[mg * 2 + 1] = fmaf(c[mg][t][2], c[mg][t][2], fmaf(c[mg][t][3], c[mg][t][3], qs[mg * 2 + 1]));
        }
#pragma unroll
    for (int i = 0; i < 4; i++) {
        s[i]  += __shfl_xor_sync(~0u, s[i], 1);  s[i]  += __shfl_xor_sync(~0u, s[i], 2);
        qs[i] += __shfl_xor_sync(~0u, qs[i], 1); qs[i] += __shfl_xor_sync(~0u, qs[i], 2);
    }

    float* st = (float*)(smem + SM_STATS);   // [nh][sum(128) | sq(128)]
    if (q == 0) {
#pragma unroll
        for (int mg = 0; mg < 2; mg++) {
            int r0 = rg * 32 + mg * 16 + ar;
            st[nh * 256 + r0]           = s[mg * 2];
            st[nh * 256 + 128 + r0]     = qs[mg * 2];
            st[nh * 256 + r0 + 8]       = s[mg * 2 + 1];
            st[nh * 256 + 128 + r0 + 8] = qs[mg * 2 + 1];
        }
    }
    __syncthreads();   // stats visible; all Aex reads of this stage done

#pragma unroll
    for (int mg = 0; mg < 2; mg++) {
        int rA = rg * 32 + mg * 16 + ar;
        int rB = rA + 8;
        float S   = st[rA] + st[256 + rA];
        float SQ  = st[128 + rA] + st[384 + rA];
        float Sb  = st[rB] + st[256 + rB];
        float SQb = st[128 + rB] + st[384 + rB];
        float mA = S  * (1.f / 128.f), vA = SQ  * (1.f / 128.f) - mA * mA, rsA = rsqrtf(vA + EPS);
        float mB = Sb * (1.f / 128.f), vB = SQb * (1.f / 128.f) - mB * mB, rsB = rsqrtf(vB + EPS);
#pragma unroll
        for (int t = 0; t < 8; t++) {
            int c0 = cb + t * 8 + q * 2;
            float g0 = lds32f(sb + gboff + (uint32_t)(c0 * 4));
            float g1 = lds32f(sb + gboff + (uint32_t)(c0 * 4) + 4);
            float b0 = lds32f(sb + gboff + 512u + (uint32_t)(c0 * 4));
            float b1 = lds32f(sb + gboff + 512u + (uint32_t)(c0 * 4) + 4);
            float xA0 = fmaxf(fmaf((c[mg][t][0] - mA) * rsA, g0, b0), 0.f);
            float xA1 = fmaxf(fmaf((c[mg][t][1] - mA) * rsA, g1, b1), 0.f);
            float xB0 = fmaxf(fmaf((c[mg][t][2] - mB) * rsB, g0, b0), 0.f);
            float xB1 = fmaxf(fmaf((c[mg][t][3] - mB) * rsB, g1, b1), 0.f);
            sts64(sb + SM_AEX + (uint32_t)((rA * AROW + c0) * 4), f2tf(xA0), f2tf(xA1));
            sts64(sb + SM_AEX + (uint32_t)((rB * AROW + c0) * 4), f2tf(xB0), f2tf(xB1));
        }
    }
    __syncthreads();   // Aex visible
}

__global__ __launch_bounds__(256, 2) void k_edge_mma(
    const float* __restrict__ agt_ctrs, const float* __restrict__ ctx_ctrs,
    const int* __restrict__ hi, const int* __restrict__ wi,
    const float* __restrict__ dist_w1, const float* __restrict__ dist_b1,
    const float* __restrict__ dist_g2, const float* __restrict__ dist_b2,
    const float* __restrict__ ctx_g1, const float* __restrict__ ctx_b1) {
    extern __shared__ char smem[];
    const uint32_t sb = smem_u32(smem);
    const int tid = threadIdx.x;
    const int w = tid >> 5, l = tid & 31, q = l & 3;
    const int rg = w >> 1, nh = w & 1;         // row group 0-3 (32 rows), col half 0-1
    const int ar = l >> 2;

    int* hi_s = (int*)(smem + SM_HIS);
    int* wi_s = (int*)(smem + SM_WIS);
    float2* d2s = (float2*)(smem + SM_D2);
    float* gbs = (float*)(smem + SM_GB);
    const int e0 = blockIdx.x * TRE;
    if (tid < TRE) {
        int h = hi[e0 + tid], ww = wi[e0 + tid];
        hi_s[tid] = h; wi_s[tid] = ww;
        float2 ac = ((const float2*)agt_ctrs)[h];
        float2 cc = ((const float2*)ctx_ctrs)[ww];
        d2s[tid] = make_float2(ac.x - cc.x, ac.y - cc.y);
    }
    // gamma/beta stash: [0:128) g2 [128:256) b2 [256:384) cg1 [384:512) cb1
    gbs[tid]       = (tid < 128) ? __ldg(dist_g2 + tid) : __ldg(dist_b2 + tid - 128);
    gbs[256 + tid] = (tid < 128) ? __ldg(ctx_g1 + tid)  : __ldg(ctx_b1 + tid - 128);
    __syncthreads();                           // ids/d2/gb visible

    // initial A = relu(d2 @ dist_w1 + b1) -> Aex as tf32 (2 cols per iter)
    for (int idx = tid; idx < TRE * 64; idx += 256) {
        int row = idx >> 6, c2 = (idx & 63) * 2;
        float2 dd = d2s[row];
        float2 w0v = __ldg((const float2*)(dist_w1 + c2));
        float2 w1v = __ldg((const float2*)(dist_w1 + D + c2));
        float2 bbv = __ldg((const float2*)(dist_b1 + c2));
        float x0 = fmaxf(fmaf(dd.x, w0v.x, fmaf(dd.y, w1v.x, bbv.x)), 0.f);
        float x1 = fmaxf(fmaf(dd.x, w0v.y, fmaf(dd.y, w1v.y, bbv.y)), 0.f);
        sts64(sb + SM_AEX + (uint32_t)((row * AROW + c2) * 4), f2tf(x0), f2tf(x1));
    }
    __syncthreads();                           // Aex visible

    float c[2][8][4];
    // ---- stage 1: @ dist_w2, GN(dist_g2,b2)+relu ----
#pragma unroll
    for (int mg = 0; mg < 2; mg++)
#pragma unroll
        for (int t = 0; t < 8; t++)
            c[mg][t][0] = c[mg][t][1] = c[mg][t][2] = c[mg][t][3] = 0.f;
    mma_stage(c, sb, (const uint4*)g_wt, rg, nh, l);
    ep_gn<false>(c, SM_GB, sb, smem, hi_s, wi_s, rg, nh, l);

    // ---- stage 2: @ ctx_w1[0:128] + qb[hi] + ctxc[wi], GN(ctx_g1,b1)+relu ----
#pragma unroll
    for (int mg = 0; mg < 2; mg++)
#pragma unroll
        for (int t = 0; t < 8; t++)
            c[mg][t][0] = c[mg][t][1] = c[mg][t][2] = c[mg][t][3] = 0.f;
    mma_stage(c, sb, (const uint4*)(g_wt + 16384), rg, nh, l);
    ep_gn<true>(c, SM_GB + 1024, sb, smem, hi_s, wi_s, rg, nh, l);

    // ---- stage 3: @ ctx_w2, scatter-add ----
#pragma unroll
    for (int mg = 0; mg < 2; mg++)
#pragma unroll
        for (int t = 0; t < 8; t++)
            c[mg][t][0] = c[mg][t][1] = c[mg][t][2] = c[mg][t][3] = 0.f;
    mma_stage(c, sb, (const uint4*)(g_wt + 32768), rg, nh, l);
    {
        const bool even = (q & 1) == 0;
#pragma unroll
        for (int mg = 0; mg < 2; mg++) {
            int r0 = rg * 32 + mg * 16 + ar;
            float* baseA = g_acc + hi_s[r0] * D + nh * 64;
            float* baseB = g_acc + hi_s[r0 + 8] * D + nh * 64;
#pragma unroll
            for (int t = 0; t < 8; t++) {
                float x0 = __shfl_xor_sync(~0u, c[mg][t][0], 1);
                float x1 = __shfl_xor_sync(~0u, c[mg][t][1], 1);
                float x2 = __shfl_xor_sync(~0u, c[mg][t][2], 1);
                float x3 = __shfl_xor_sync(~0u, c[mg][t][3], 1);
                if (even) red4(baseA + t * 8 + q * 2,       c[mg][t][0], c[mg][t][1], x0, x1);
                else      red4(baseB + t * 8 + (q - 1) * 2, x2, x3, c[mg][t][2], c[mg][t][3]);
            }
        }
    }
}

// ---------------------------------------------------------------------------
// FFMA node kernels (split so k_edge is launch #4 for ncu)
// ---------------------------------------------------------------------------
__device__ __forceinline__ void gemm_tile(const float* in_s, const float* __restrict__ W,
                                          float* wbuf, float acc[8][4], int e0, int c4, int tid) {
    const float4* Wg = reinterpret_cast<const float4*>(W);
    float4* wb = reinterpret_cast<float4*>(wbuf);
    for (int kb = 0; kb < D; kb += KC) {
        __syncthreads();
        wb[tid]      = Wg[kb * (D / 4) + tid];
        wb[tid + NT] = Wg[kb * (D / 4) + tid + NT];
        __syncthreads();
#pragma unroll
        for (int kk = 0; kk < KC; kk++) {
            float4 w = wb[kk * (D / 4) + c4];
#pragma unroll
            for (int i = 0; i < 8; i++) {
                float h = in_s[(e0 + i) * D + kb + kk];
                acc[i][0] = fmaf(h, w.x, acc[i][0]);
                acc[i][1] = fmaf(h, w.y, acc[i][1]);
                acc[i][2] = fmaf(h, w.z, acc[i][2]);
                acc[i][3] = fmaf(h, w.w, acc[i][3]);
            }
        }
    }
}

__device__ __forceinline__ void zero_acc(float acc[8][4]) {
#pragma unroll
    for (int i = 0; i < 8; i++)
#pragma unroll
        for (int j = 0; j < 4; j++) acc[i][j] = 0.f;
}

__device__ __forceinline__ void store_acc(float* io, const float acc[8][4], int e0, int c4) {
#pragma unroll
    for (int i = 0; i < 8; i++) {
        float4 v = make_float4(acc[i][0], acc[i][1], acc[i][2], acc[i][3]);
        *reinterpret_cast<float4*>(&io[(e0 + i) * D + c4 * 4]) = v;
    }
}

__device__ __forceinline__ void gn_rows(float* io, const float* __restrict__ g,
                                        const float* __restrict__ b, bool do_relu, int tid) {
    int lane = tid & 31, w = tid >> 5;
    for (int r = w; r < TR; r += 8) {
        float v[4], s = 0.f, sq = 0.f;
#pragma unroll
        for (int j = 0; j < 4; j++) {
            v[j] = io[r * D + lane + 32 * j];
            s += v[j]; sq += v[j] * v[j];
        }
#pragma unroll
        for (int o = 16; o > 0; o >>= 1) {
            s  += __shfl_xor_sync(0xffffffffu, s, o);
            sq += __shfl_xor_sync(0xffffffffu, sq, o);
        }
        float mean = s * (1.f / D);
        float var  = sq * (1.f / D) - mean * mean;
        float rstd = rsqrtf(var + EPS);
#pragma unroll
        for (int j = 0; j < 4; j++) {
            int c = lane + 32 * j;
            float x = (v[j] - mean) * rstd * g[c] + b[c];
            io[r * D + c] = do_relu ? fmaxf(x, 0.f) : x;
        }
    }
}

__global__ __launch_bounds__(NT) void k_nodes_a(const float* __restrict__ agts,
                                                const float* __restrict__ query_w,
                                                const float* __restrict__ query_g,
                                                const float* __restrict__ query_b,
                                                const float* __restrict__ ctx_w1,
                                                const float* __restrict__ agt_w) {
    __shared__ float io[TR * D];
    __shared__ float wbuf[KC * D];
    int tid = threadIdx.x;
    int task = blockIdx.x >> 8;
    int r0 = (blockIdx.x & 255) * TR;
    int lane = tid & 31, wid = tid >> 5;
    int c4 = lane, e0 = wid * 8;
    float acc[8][4];

    for (int idx = tid; idx < TR * D; idx += NT) io[idx] = agts[r0 * D + idx];

    if (task == 0) {
        zero_acc(acc);
        gemm_tile(io, query_w, wbuf, acc, e0, c4, tid);
        __syncthreads();
        store_acc(io, acc, e0, c4);
        __syncthreads();
        gn_rows(io, query_g, query_b, true, tid);
        __syncthreads();
        zero_acc(acc);
        gemm_tile(io, ctx_w1 + D * D, wbuf, acc, e0, c4, tid);
#pragma unroll
        for (int i = 0; i < 8; i++) {
            float4 v = make_float4(acc[i][0], acc[i][1], acc[i][2], acc[i][3]);
            *reinterpret_cast<float4*>(&g_qb[(r0 + e0 + i) * D + c4 * 4]) = v;
        }
    } else {
        zero_acc(acc);
        gemm_tile(io, agt_w, wbuf, acc, e0, c4, tid);
#pragma unroll
        for (int i = 0; i < 8; i++) {
            float4 v = make_float4(acc[i][0], acc[i][1], acc[i][2], acc[i][3]);
            *reinterpret_cast<float4*>(&g_acc[(r0 + e0 + i) * D + c4 * 4]) = v;
        }
    }
}

__global__ __launch_bounds__(NT) void k_nodes_b(const float* __restrict__ ctx,
                                                const float* __restrict__ ctx_w1) {
    __shared__ float io[TR * D];
    __shared__ float wbuf[KC * D];
    int tid = threadIdx.x;
    int r0 = blockIdx.x * TR;
    int lane = tid & 31, wid = tid >> 5;
    int c4 = lane, e0 = wid * 8;
    float acc[8][4];

    for (int idx = tid; idx < TR * D; idx += NT) io[idx] = ctx[r0 * D + idx];
    zero_acc(acc);
    gemm_tile(io, ctx_w1 + 2 * D * D, wbuf, acc, e0, c4, tid);
#pragma unroll
    for (int i = 0; i < 8; i++) {
        float4 v = make_float4(acc[i][0], acc[i][1], acc[i][2], acc[i][3]);
        *reinterpret_cast<float4*>(&g_ctxc[(r0 + e0 + i) * D + c4 * 4]) = v;
    }
}

__global__ __launch_bounds__(NT) void k_final(const float* __restrict__ agts,
                                              const float* __restrict__ norm_g,
                                              const float* __restrict__ norm_b,
                                              const float* __restrict__ lin_w,
                                              const float* __restrict__ lin_g,
                                              const float* __restrict__ lin_b,
                                              float* __restrict__ out) {
    __shared__ float io[TR * D];
    __shared__ float wbuf[KC * D];
    int tid = threadIdx.x;
    int r0 = blockIdx.x * TR;
    int lane = tid & 31, wid = tid >> 5;
    int c4 = lane, e0 = wid * 8;

    for (int idx = tid; idx < TR * D; idx += NT) io[idx] = g_acc[r0 * D + idx];
    __syncthreads();
    gn_rows(io, norm_g, norm_b, true, tid);
    __syncthreads();

    float acc[8][4];
    zero_acc(acc);
    gemm_tile(io, lin_w, wbuf, acc, e0, c4, tid);
    __syncthreads();
    store_acc(io, acc, e0, c4);
    __syncthreads();

    for (int r = wid; r < TR; r += 8) {
        float v[4], s = 0.f, sq = 0.f;
#pragma unroll
        for (int j = 0; j < 4; j++) {
            v[j] = io[r * D + lane + 32 * j];
            s += v[j]; sq += v[j] * v[j];
        }
#pragma unroll
        for (int o = 16; o > 0; o >>= 1) {
            s  += __shfl_xor_sync(0xffffffffu, s, o);
            sq += __shfl_xor_sync(0xffffffffu, sq, o);
        }
        float mean = s * (1.f / D);
        float var  = sq * (1.f / D) - mean * mean;
        float rstd = rsqrtf(var + EPS);
#pragma unroll
        for (int j = 0; j < 4; j++) {
            int c = lane + 32 * j;
            float x = (v[j] - mean) * rstd * lin_g[c] + lin_b[c];
            float res = agts[(r0 + r) * D + c];
            out[(r0 + r) * D + c] = fmaxf(x + res, 0.f);
        }
    }
}

// ---------------------------------------------------------------------------
extern "C" void kernel_launch(void* const* d_in, const int* in_sizes, int n_in,
                              void* d_out, int out_size) {
    const float* agts     = (const float*)d_in[0];
    const float* ctx      = (const float*)d_in[1];
    const float* agt_ctrs = (const float*)d_in[2];
    const float* ctx_ctrs = (const float*)d_in[3];
    const int*   hi       = (const int*)d_in[4];
    const int*   wi       = (const int*)d_in[5];
    const float* dist_w1  = (const float*)d_in[6];
    const float* dist_b1  = (const float*)d_in[7];
    const float* dist_w2  = (const float*)d_in[8];
    const float* dist_g2  = (const float*)d_in[9];
    const float* dist_b2  = (const float*)d_in[10];
    const float* query_w  = (const float*)d_in[11];
    const float* query_g  = (const float*)d_in[12];
    const float* query_b  = (const float*)d_in[13];
    const float* ctx_w1   = (const float*)d_in[14];
    const float* ctx_g1   = (const float*)d_in[15];
    const float* ctx_b1   = (const float*)d_in[16];
    const float* ctx_w2   = (const float*)d_in[17];
    const float* agt_w    = (const float*)d_in[18];
    const float* norm_g   = (const float*)d_in[19];
    const float* norm_b   = (const float*)d_in[20];
    const float* lin_w    = (const float*)d_in[21];
    const float* lin_g    = (const float*)d_in[22];
    const float* lin_b    = (const float*)d_in[23];
    float* out = (float*)d_out;

    cudaFuncSetAttribute(k_edge_mma, cudaFuncAttributeMaxDynamicSharedMemorySize, SMEM_EDGE);

    k_prep<<<dim3(64, 3), 256>>>(dist_w2, ctx_w1, ctx_w2);                 // launch 1
    k_nodes_a<<<512, NT>>>(agts, query_w, query_g, query_b, ctx_w1, agt_w);// launch 2
    k_nodes_b<<<256, NT>>>(ctx, ctx_w1);                                   // launch 3
    k_edge_mma<<<NE / TRE, 256, SMEM_EDGE>>>(agt_ctrs, ctx_ctrs, hi, wi,   // launch 4 (ncu)
                                             dist_w1, dist_b1,
                                             dist_g2, dist_b2,
                                             ctx_g1, ctx_b1);
    k_final<<<NA / TR, NT>>>(agts, norm_g, norm_b, lin_w, lin_g, lin_b, out);
}

// round 15
// speedup vs baseline: 1.6603x; 1.3332x over previous
#include <cuda_runtime.h>
#include <cuda_bf16.h>
#include <cuda_fp16.h>
#include <cstdint>

#define D     128
#define NA    16384
#define NC    16384
#define NE    524288
#define TR    64
#define NT    256
#define KC    16
#define TRE   128     // edges per block (4 row-groups x 32 rows, 2 col-halves; 8 warps)
#define EPS   1e-5f
#define AROWH 68      // u32 (half2) words per Aex row; 68 mod 32 = 4 -> conflict-free

// ---------------------------------------------------------------------------
// device scratch (no allocation)
// ---------------------------------------------------------------------------
__device__ __align__(16) float g_qb[NA * D];      // relu(GN(agts@query_w)) @ ctx_w1[128:256]
__device__ __align__(16) float g_ctxc[NC * D];    // ctx @ ctx_w1[256:384]
__device__ __align__(16) float g_acc[NA * D];     // agts@agt_w + scattered edge output
__device__ __align__(16) uint32_t g_wt[3 * 8192]; // fp16 W images, FRAGMENT-ORDERED (32KB each)

// ---------------------------------------------------------------------------
// helpers
// ---------------------------------------------------------------------------
__device__ __forceinline__ uint32_t smem_u32(const void* p) {
    uint32_t a;
    asm("{ .reg .u64 t; cvta.to.shared.u64 t, %1; cvt.u32.u64 %0, t; }" : "=r"(a) : "l"(p));
    return a;
}

__device__ __forceinline__ uint32_t h2pack(float x0, float x1) {
    __half2 h = __floats2half2_rn(x0, x1);
    return *reinterpret_cast<uint32_t*>(&h);
}

__device__ __forceinline__ void mma_f16(float c[4], const uint32_t a[4], uint32_t b0, uint32_t b1) {
    asm volatile(
        "mma.sync.aligned.m16n8k16.row.col.f32.f16.f16.f32 "
        "{%0,%1,%2,%3}, {%4,%5,%6,%7}, {%8,%9}, {%0,%1,%2,%3};"
        : "+f"(c[0]), "+f"(c[1]), "+f"(c[2]), "+f"(c[3])
        : "r"(a[0]), "r"(a[1]), "r"(a[2]), "r"(a[3]), "r"(b0), "r"(b1));
}

__device__ __forceinline__ uint32_t lds32(uint32_t a) {
    uint32_t v;
    asm volatile("ld.shared.b32 %0, [%1];" : "=r"(v) : "r"(a));
    return v;
}
__device__ __forceinline__ float lds32f(uint32_t a) {
    float v;
    asm volatile("ld.shared.f32 %0, [%1];" : "=f"(v) : "r"(a));
    return v;
}
__device__ __forceinline__ void sts32(uint32_t a, uint32_t x) {
    asm volatile("st.shared.b32 [%0], %1;" :: "r"(a), "r"(x) : "memory");
}

__device__ __forceinline__ void red4(float* p, float a, float b, float c, float d) {
    asm volatile("red.global.add.v4.f32 [%0], {%1,%2,%3,%4};"
                 :: "l"(p), "f"(a), "f"(b), "f"(c), "f"(d) : "memory");
}

// ---------------------------------------------------------------------------
// k_edge smem map (bytes): NO W buffer — B comes from L1 via LDG
// ---------------------------------------------------------------------------
#define SM_AEX    0        /* 128 rows x AROWH u32 = 34816B */
#define SM_STATS  34816    /* 512 floats */
#define SM_GB     36864    /* 512 floats: g2,b2,cg1,cb1 */
#define SM_HIS    38912
#define SM_WIS    39424
#define SM_D2     39936
#define SMEM_EDGE 40960

// Fragment-ordered fp16 W image for mma.m16n8k16 (row.col):
//   element (k, n):
//     kc = k>>4, kl = k&15, bk = (kl>>1)&3, h = kl&1, kh = kl>>3
//     nh = n>>6, p = (n>>3)&7, bn = n&7
//     lane = bn*4 + bk;  j = kh*2 + (p>>2);  e = p&3
//   u32 index within matrix = nh*4096 + kc*512 + j*128 + lane*4 + e; half h within.
__global__ void k_prep(const float* __restrict__ w0, const float* __restrict__ w1,
                       const float* __restrict__ w2) {
    int m = blockIdx.y;
    const float* src = (m == 0) ? w0 : (m == 1 ? w1 : w2);
    int idx = blockIdx.x * 256 + threadIdx.x;    // k*128 + n
    int k = idx >> 7, n = idx & 127;
    int kc = k >> 4, kl = k & 15;
    int bk = (kl >> 1) & 3, h = kl & 1, kh = kl >> 3;
    int nh = n >> 6, p = (n >> 3) & 7, bn = n & 7;
    int j = kh * 2 + (p >> 2);
    int e = p & 3;
    int l = bn * 4 + bk;
    int du = nh * 4096 + kc * 512 + j * 128 + l * 4 + e;
    __half hv = __float2half_rn(src[idx]);
    ((uint16_t*)(g_wt + m * 8192))[du * 2 + h] = *reinterpret_cast<uint16_t*>(&hv);
}

// C[2 mg][8 tiles][4] += A[32 rows, fp16 in smem] @ W[fp16 B frags via LDG from L1]
// warp rows rg*32..+31, cols nh*64..+63.  8 k16-chunks.
__device__ __forceinline__ void mma_stage(float c[2][8][4], uint32_t sb,
                                          const uint4* __restrict__ wg,
                                          int rg, int nh, int l) {
    const int ar = l >> 2, bk = l & 3;
    const uint32_t a0base = sb + SM_AEX + (uint32_t)(((rg * 32 + ar) * AROWH + bk) * 4);
    const uint4* bbase = wg + nh * 1024 + l;   // uint4 idx: nh*1024 + kc*128 + j*32 + l
#pragma unroll
    for (int kc = 0; kc < 8; kc++) {
        uint32_t a[2][4];
#pragma unroll
        for (int mg = 0; mg < 2; mg++) {
            uint32_t aa = a0base + (uint32_t)(mg * 16 * AROWH * 4 + kc * 32);
            a[mg][0] = lds32(aa);
            a[mg][2] = lds32(aa + 16);
            a[mg][1] = lds32(aa + 8 * AROWH * 4);
            a[mg][3] = lds32(aa + 8 * AROWH * 4 + 16);
        }
        {   // p = 0..3
            uint4 B0 = __ldg(bbase + kc * 128);        // b0 p0..3
            uint4 B2 = __ldg(bbase + kc * 128 + 64);   // b1 p0..3
            mma_f16(c[0][0], a[0], B0.x, B2.x);
            mma_f16(c[0][1], a[0], B0.y, B2.y);
            mma_f16(c[0][2], a[0], B0.z, B2.z);
            mma_f16(c[0][3], a[0], B0.w, B2.w);
            mma_f16(c[1][0], a[1], B0.x, B2.x);
            mma_f16(c[1][1], a[1], B0.y, B2.y);
            mma_f16(c[1][2], a[1], B0.z, B2.z);
            mma_f16(c[1][3], a[1], B0.w, B2.w);
        }
        {   // p = 4..7
            uint4 B1 = __ldg(bbase + kc * 128 + 32);   // b0 p4..7
            uint4 B3 = __ldg(bbase + kc * 128 + 96);   // b1 p4..7
            mma_f16(c[0][4], a[0], B1.x, B3.x);
            mma_f16(c[0][5], a[0], B1.y, B3.y);
            mma_f16(c[0][6], a[0], B1.z, B3.z);
            mma_f16(c[0][7], a[0], B1.w, B3.w);
            mma_f16(c[1][4], a[1], B1.x, B3.x);
            mma_f16(c[1][5], a[1], B1.y, B3.y);
            mma_f16(c[1][6], a[1], B1.z, B3.z);
            mma_f16(c[1][7], a[1], B1.w, B3.w);
        }
    }
}

// GN(+relu) epilogue: (gather) -> stats -> barrier -> normalize (gb from smem)
// -> Aex(fp16 pairs) -> barrier
template <bool GATHER>
__device__ __forceinline__ void ep_gn(float c[2][8][4],
                                      uint32_t gboff,   // smem byte offset of gamma (beta at +512)
                                      uint32_t sb, char* smem,
                                      const int* hi_s, const int* wi_s,
                                      int rg, int nh, int l) {
    const int q = l & 3;
    const int ar = l >> 2;
    const int cb = nh * 64;

    if (GATHER) {
#pragma unroll
        for (int mg = 0; mg < 2; mg++) {
            int r0 = rg * 32 + mg * 16 + ar;
            const float* qA = g_qb   + hi_s[r0] * D + cb;
            const float* cA = g_ctxc + wi_s[r0] * D + cb;
            const float* qB = g_qb   + hi_s[r0 + 8] * D + cb;
            const float* cB = g_ctxc + wi_s[r0 + 8] * D + cb;
#pragma unroll
            for (int t = 0; t < 8; t++) {
                float2 a1 = __ldg((const float2*)(qA + t * 8) + q);
                float2 a2 = __ldg((const float2*)(cA + t * 8) + q);
                float2 b1 = __ldg((const float2*)(qB + t * 8) + q);
                float2 b2 = __ldg((const float2*)(cB + t * 8) + q);
                c[mg][t][0] += a1.x + a2.x;  c[mg][t][1] += a1.y + a2.y;
                c[mg][t][2] += b1.x + b2.x;  c[mg][t][3] += b1.y + b2.y;
            }
        }
    }
    float s[4] = {0.f, 0.f, 0.f, 0.f}, qs[4] = {0.f, 0.f, 0.f, 0.f};
#pragma unroll
    for (int mg = 0; mg < 2; mg++)
#pragma unroll
        for (int t = 0; t < 8; t++) {
            s[mg * 2]     += c[mg][t][0] + c[mg][t][1];
            qs[mg * 2]     = fmaf(c[mg][t][0], c[mg][t][0], fmaf(c[mg][t][1], c[mg][t][1], qs[mg * 2]));
            s[mg * 2 + 1] += c[mg][t][2] + c[mg][t][3];
            qs[mg * 2 + 1] = fmaf(c[mg][t][2], c[mg][t][2], fmaf(c[mg][t][3], c[mg][t][3], qs[mg * 2 + 1]));
        }
#pragma unroll
    for (int i = 0; i < 4; i++) {
        s[i]  += __shfl_xor_sync(~0u, s[i], 1);  s[i]  += __shfl_xor_sync(~0u, s[i], 2);
        qs[i] += __shfl_xor_sync(~0u, qs[i], 1); qs[i] += __shfl_xor_sync(~0u, qs[i], 2);
    }

    float* st = (float*)(smem + SM_STATS);   // [nh][sum(128) | sq(128)]
    if (q == 0) {
#pragma unroll
        for (int mg = 0; mg < 2; mg++) {
            int r0 = rg * 32 + mg * 16 + ar;
            st[nh * 256 + r0]           = s[mg * 2];
            st[nh * 256 + 128 + r0]     = qs[mg * 2];
            st[nh * 256 + r0 + 8]       = s[mg * 2 + 1];
            st[nh * 256 + 128 + r0 + 8] = qs[mg * 2 + 1];
        }
    }
    __syncthreads();   // stats visible; all Aex reads of this stage done

#pragma unroll
    for (int mg = 0; mg < 2; mg++) {
        int rA = rg * 32 + mg * 16 + ar;
        int rB = rA + 8;
        float S   = st[rA] + st[256 + rA];
        float SQ  = st[128 + rA] + st[384 + rA];
        float Sb  = st[rB] + st[256 + rB];
        float SQb = st[128 + rB] + st[384 + rB];
        float mA = S  * (1.f / 128.f), vA = SQ  * (1.f / 128.f) - mA * mA, rsA = rsqrtf(vA + EPS);
        float mB = Sb * (1.f / 128.f), vB = SQb * (1.f / 128.f) - mB * mB, rsB = rsqrtf(vB + EPS);
#pragma unroll
        for (int t = 0; t < 8; t++) {
            int c0 = cb + t * 8 + q * 2;
            float g0 = lds32f(sb + gboff + (uint32_t)(c0 * 4));
            float g1 = lds32f(sb + gboff + (uint32_t)(c0 * 4) + 4);
            float b0 = lds32f(sb + gboff + 512u + (uint32_t)(c0 * 4));
            float b1 = lds32f(sb + gboff + 512u + (uint32_t)(c0 * 4) + 4);
            float xA0 = fmaxf(fmaf((c[mg][t][0] - mA) * rsA, g0, b0), 0.f);
            float xA1 = fmaxf(fmaf((c[mg][t][1] - mA) * rsA, g1, b1), 0.f);
            float xB0 = fmaxf(fmaf((c[mg][t][2] - mB) * rsB, g0, b0), 0.f);
            float xB1 = fmaxf(fmaf((c[mg][t][3] - mB) * rsB, g1, b1), 0.f);
            int wA = rA * AROWH + (c0 >> 1);
            int wB = rB * AROWH + (c0 >> 1);
            sts32(sb + SM_AEX + (uint32_t)(wA * 4), h2pack(xA0, xA1));
            sts32(sb + SM_AEX + (uint32_t)(wB * 4), h2pack(xB0, xB1));
        }
    }
    __syncthreads();   // Aex visible
}

__global__ __launch_bounds__(256, 2) void k_edge_mma(
    const float* __restrict__ agt_ctrs, const float* __restrict__ ctx_ctrs,
    const int* __restrict__ hi, const int* __restrict__ wi,
    const float* __restrict__ dist_w1, const float* __restrict__ dist_b1,
    const float* __restrict__ dist_g2, const float* __restrict__ dist_b2,
    const float* __restrict__ ctx_g1, const float* __restrict__ ctx_b1) {
    extern __shared__ char smem[];
    const uint32_t sb = smem_u32(smem);
    const int tid = threadIdx.x;
    const int w = tid >> 5, l = tid & 31, q = l & 3;
    const int rg = w >> 1, nh = w & 1;         // row group 0-3 (32 rows), col half 0-1
    const int ar = l >> 2;

    int* hi_s = (int*)(smem + SM_HIS);
    int* wi_s = (int*)(smem + SM_WIS);
    float2* d2s = (float2*)(smem + SM_D2);
    float* gbs = (float*)(smem + SM_GB);
    const int e0 = blockIdx.x * TRE;
    if (tid < TRE) {
        int h = hi[e0 + tid], ww = wi[e0 + tid];
        hi_s[tid] = h; wi_s[tid] = ww;
        float2 ac = ((const float2*)agt_ctrs)[h];
        float2 cc = ((const float2*)ctx_ctrs)[ww];
        d2s[tid] = make_float2(ac.x - cc.x, ac.y - cc.y);
    }
    // gamma/beta stash: [0:128) g2 [128:256) b2 [256:384) cg1 [384:512) cb1
    gbs[tid]       = (tid < 128) ? __ldg(dist_g2 + tid) : __ldg(dist_b2 + tid - 128);
    gbs[256 + tid] = (tid < 128) ? __ldg(ctx_g1 + tid)  : __ldg(ctx_b1 + tid - 128);
    __syncthreads();                           // ids/d2/gb visible

    // initial A = relu(d2 @ dist_w1 + b1) -> Aex as half2 words
    for (int idx = tid; idx < TRE * 64; idx += 256) {
        int row = idx >> 6, wrd = idx & 63;
        int c2 = wrd * 2;
        float2 dd = d2s[row];
        float2 w0v = __ldg((const float2*)(dist_w1 + c2));
        float2 w1v = __ldg((const float2*)(dist_w1 + D + c2));
        float2 bbv = __ldg((const float2*)(dist_b1 + c2));
        float x0 = fmaxf(fmaf(dd.x, w0v.x, fmaf(dd.y, w1v.x, bbv.x)), 0.f);
        float x1 = fmaxf(fmaf(dd.x, w0v.y, fmaf(dd.y, w1v.y, bbv.y)), 0.f);
        sts32(sb + SM_AEX + (uint32_t)((row * AROWH + wrd) * 4), h2pack(x0, x1));
    }
    __syncthreads();                           // Aex visible

    float c[2][8][4];
    // ---- stage 1: @ dist_w2, GN(dist_g2,b2)+relu ----
#pragma unroll
    for (int mg = 0; mg < 2; mg++)
#pragma unroll
        for (int t = 0; t < 8; t++)
            c[mg][t][0] = c[mg][t][1] = c[mg][t][2] = c[mg][t][3] = 0.f;
    mma_stage(c, sb, (const uint4*)g_wt, rg, nh, l);
    ep_gn<false>(c, SM_GB, sb, smem, hi_s, wi_s, rg, nh, l);

    // ---- stage 2: @ ctx_w1[0:128] + qb[hi] + ctxc[wi], GN(ctx_g1,b1)+relu ----
#pragma unroll
    for (int mg = 0; mg < 2; mg++)
#pragma unroll
        for (int t = 0; t < 8; t++)
            c[mg][t][0] = c[mg][t][1] = c[mg][t][2] = c[mg][t][3] = 0.f;
    mma_stage(c, sb, (const uint4*)(g_wt + 8192), rg, nh, l);
    ep_gn<true>(c, SM_GB + 1024, sb, smem, hi_s, wi_s, rg, nh, l);

    // ---- stage 3: @ ctx_w2, scatter-add ----
#pragma unroll
    for (int mg = 0; mg < 2; mg++)
#pragma unroll
        for (int t = 0; t < 8; t++)
            c[mg][t][0] = c[mg][t][1] = c[mg][t][2] = c[mg][t][3] = 0.f;
    mma_stage(c, sb, (const uint4*)(g_wt + 16384), rg, nh, l);
    {
        const int q2 = l & 3;
        const bool even = (q2 & 1) == 0;
#pragma unroll
        for (int mg = 0; mg < 2; mg++) {
            int r0 = rg * 32 + mg * 16 + ar;
            float* baseA = g_acc + hi_s[r0] * D + nh * 64;
            float* baseB = g_acc + hi_s[r0 + 8] * D + nh * 64;
#pragma unroll
            for (int t = 0; t < 8; t++) {
                float x0 = __shfl_xor_sync(~0u, c[mg][t][0], 1);
                float x1 = __shfl_xor_sync(~0u, c[mg][t][1], 1);
                float x2 = __shfl_xor_sync(~0u, c[mg][t][2], 1);
                float x3 = __shfl_xor_sync(~0u, c[mg][t][3], 1);
                if (even) red4(baseA + t * 8 + q2 * 2,       c[mg][t][0], c[mg][t][1], x0, x1);
                else      red4(baseB + t * 8 + (q2 - 1) * 2, x2, x3, c[mg][t][2], c[mg][t][3]);
            }
        }
    }
}

// ---------------------------------------------------------------------------
// FFMA node kernels (split so k_edge is launch #4 for ncu)
// ---------------------------------------------------------------------------
__device__ __forceinline__ void gemm_tile(const float* in_s, const float* __restrict__ W,
                                          float* wbuf, float acc[8][4], int e0, int c4, int tid) {
    const float4* Wg = reinterpret_cast<const float4*>(W);
    float4* wb = reinterpret_cast<float4*>(wbuf);
    for (int kb = 0; kb < D; kb += KC) {
        __syncthreads();
        wb[tid]      = Wg[kb * (D / 4) + tid];
        wb[tid + NT] = Wg[kb * (D / 4) + tid + NT];
        __syncthreads();
#pragma unroll
        for (int kk = 0; kk < KC; kk++) {
            float4 w = wb[kk * (D / 4) + c4];
#pragma unroll
            for (int i = 0; i < 8; i++) {
                float h = in_s[(e0 + i) * D + kb + kk];
                acc[i][0] = fmaf(h, w.x, acc[i][0]);
                acc[i][1] = fmaf(h, w.y, acc[i][1]);
                acc[i][2] = fmaf(h, w.z, acc[i][2]);
                acc[i][3] = fmaf(h, w.w, acc[i][3]);
            }
        }
    }
}

__device__ __forceinline__ void zero_acc(float acc[8][4]) {
#pragma unroll
    for (int i = 0; i < 8; i++)
#pragma unroll
        for (int j = 0; j < 4; j++) acc[i][j] = 0.f;
}

__device__ __forceinline__ void store_acc(float* io, const float acc[8][4], int e0, int c4) {
#pragma unroll
    for (int i = 0; i < 8; i++) {
        float4 v = make_float4(acc[i][0], acc[i][1], acc[i][2], acc[i][3]);
        *reinterpret_cast<float4*>(&io[(e0 + i) * D + c4 * 4]) = v;
    }
}

__device__ __forceinline__ void gn_rows(float* io, const float* __restrict__ g,
                                        const float* __restrict__ b, bool do_relu, int tid) {
    int lane = tid & 31, w = tid >> 5;
    for (int r = w; r < TR; r += 8) {
        float v[4], s = 0.f, sq = 0.f;
#pragma unroll
        for (int j = 0; j < 4; j++) {
            v[j] = io[r * D + lane + 32 * j];
            s += v[j]; sq += v[j] * v[j];
        }
#pragma unroll
        for (int o = 16; o > 0; o >>= 1) {
            s  += __shfl_xor_sync(0xffffffffu, s, o);
            sq += __shfl_xor_sync(0xffffffffu, sq, o);
        }
        float mean = s * (1.f / D);
        float var  = sq * (1.f / D) - mean * mean;
        float rstd = rsqrtf(var + EPS);
#pragma unroll
        for (int j = 0; j < 4; j++) {
            int c = lane + 32 * j;
            float x = (v[j] - mean) * rstd * g[c] + b[c];
            io[r * D + c] = do_relu ? fmaxf(x, 0.f) : x;
        }
    }
}

__global__ __launch_bounds__(NT) void k_nodes_a(const float* __restrict__ agts,
                                                const float* __restrict__ query_w,
                                                const float* __restrict__ query_g,
                                                const float* __restrict__ query_b,
                                                const float* __restrict__ ctx_w1,
                                                const float* __restrict__ agt_w) {
    __shared__ float io[TR * D];
    __shared__ float wbuf[KC * D];
    int tid = threadIdx.x;
    int task = blockIdx.x >> 8;
    int r0 = (blockIdx.x & 255) * TR;
    int lane = tid & 31, wid = tid >> 5;
    int c4 = lane, e0 = wid * 8;
    float acc[8][4];

    for (int idx = tid; idx < TR * D; idx += NT) io[idx] = agts[r0 * D + idx];

    if (task == 0) {
        zero_acc(acc);
        gemm_tile(io, query_w, wbuf, acc, e0, c4, tid);
        __syncthreads();
        store_acc(io, acc, e0, c4);
        __syncthreads();
        gn_rows(io, query_g, query_b, true, tid);
        __syncthreads();
        zero_acc(acc);
        gemm_tile(io, ctx_w1 + D * D, wbuf, acc, e0, c4, tid);
#pragma unroll
        for (int i = 0; i < 8; i++) {
            float4 v = make_float4(acc[i][0], acc[i][1], acc[i][2], acc[i][3]);
            *reinterpret_cast<float4*>(&g_qb[(r0 + e0 + i) * D + c4 * 4]) = v;
        }
    } else {
        zero_acc(acc);
        gemm_tile(io, agt_w, wbuf, acc, e0, c4, tid);
#pragma unroll
        for (int i = 0; i < 8; i++) {
            float4 v = make_float4(acc[i][0], acc[i][1], acc[i][2], acc[i][3]);
            *reinterpret_cast<float4*>(&g_acc[(r0 + e0 + i) * D + c4 * 4]) = v;
        }
    }
}

__global__ __launch_bounds__(NT) void k_nodes_b(const float* __restrict__ ctx,
                                                const float* __restrict__ ctx_w1) {
    __shared__ float io[TR * D];
    __shared__ float wbuf[KC * D];
    int tid = threadIdx.x;
    int r0 = blockIdx.x * TR;
    int lane = tid & 31, wid = tid >> 5;
    int c4 = lane, e0 = wid * 8;
    float acc[8][4];

    for (int idx = tid; idx < TR * D; idx += NT) io[idx] = ctx[r0 * D + idx];
    zero_acc(acc);
    gemm_tile(io, ctx_w1 + 2 * D * D, wbuf, acc, e0, c4, tid);
#pragma unroll
    for (int i = 0; i < 8; i++) {
        float4 v = make_float4(acc[i][0], acc[i][1], acc[i][2], acc[i][3]);
        *reinterpret_cast<float4*>(&g_ctxc[(r0 + e0 + i) * D + c4 * 4]) = v;
    }
}

__global__ __launch_bounds__(NT) void k_final(const float* __restrict__ agts,
                                              const float* __restrict__ norm_g,
                                              const float* __restrict__ norm_b,
                                              const float* __restrict__ lin_w,
                                              const float* __restrict__ lin_g,
                                              const float* __restrict__ lin_b,
                                              float* __restrict__ out) {
    __shared__ float io[TR * D];
    __shared__ float wbuf[KC * D];
    int tid = threadIdx.x;
    int r0 = blockIdx.x * TR;
    int lane = tid & 31, wid = tid >> 5;
    int c4 = lane, e0 = wid * 8;

    for (int idx = tid; idx < TR * D; idx += NT) io[idx] = g_acc[r0 * D + idx];
    __syncthreads();
    gn_rows(io, norm_g, norm_b, true, tid);
    __syncthreads();

    float acc[8][4];
    zero_acc(acc);
    gemm_tile(io, lin_w, wbuf, acc, e0, c4, tid);
    __syncthreads();
    store_acc(io, acc, e0, c4);
    __syncthreads();

    for (int r = wid; r < TR; r += 8) {
        float v[4], s = 0.f, sq = 0.f;
#pragma unroll
        for (int j = 0; j < 4; j++) {
            v[j] = io[r * D + lane + 32 * j];
            s += v[j]; sq += v[j] * v[j];
        }
#pragma unroll
        for (int o = 16; o > 0; o >>= 1) {
            s  += __shfl_xor_sync(0xffffffffu, s, o);
            sq += __shfl_xor_sync(0xffffffffu, sq, o);
        }
        float mean = s * (1.f / D);
        float var  = sq * (1.f / D) - mean * mean;
        float rstd = rsqrtf(var + EPS);
#pragma unroll
        for (int j = 0; j < 4; j++) {
            int c = lane + 32 * j;
            float x = (v[j] - mean) * rstd * lin_g[c] + lin_b[c];
            float res = agts[(r0 + r) * D + c];
            out[(r0 + r) * D + c] = fmaxf(x + res, 0.f);
        }
    }
}

// ---------------------------------------------------------------------------
extern "C" void kernel_launch(void* const* d_in, const int* in_sizes, int n_in,
                              void* d_out, int out_size) {
    const float* agts     = (const float*)d_in[0];
    const float* ctx      = (const float*)d_in[1];
    const float* agt_ctrs = (const float*)d_in[2];
    const float* ctx_ctrs = (const float*)d_in[3];
    const int*   hi       = (const int*)d_in[4];
    const int*   wi       = (const int*)d_in[5];
    const float* dist_w1  = (const float*)d_in[6];
    const float* dist_b1  = (const float*)d_in[7];
    const float* dist_w2  = (const float*)d_in[8];
    const float* dist_g2  = (const float*)d_in[9];
    const float* dist_b2  = (const float*)d_in[10];
    const float* query_w  = (const float*)d_in[11];
    const float* query_g  = (const float*)d_in[12];
    const float* query_b  = (const float*)d_in[13];
    const float* ctx_w1   = (const float*)d_in[14];
    const float* ctx_g1   = (const float*)d_in[15];
    const float* ctx_b1   = (const float*)d_in[16];
    const float* ctx_w2   = (const float*)d_in[17];
    const float* agt_w    = (const float*)d_in[18];
    const float* norm_g   = (const float*)d_in[19];
    const float* norm_b   = (const float*)d_in[20];
    const float* lin_w    = (const float*)d_in[21];
    const float* lin_g    = (const float*)d_in[22];
    const float* lin_b    = (const float*)d_in[23];
    float* out = (float*)d_out;

    cudaFuncSetAttribute(k_edge_mma, cudaFuncAttributeMaxDynamicSharedMemorySize, SMEM_EDGE);

    k_prep<<<dim3(64, 3), 256>>>(dist_w2, ctx_w1, ctx_w2);                 // launch 1
    k_nodes_a<<<512, NT>>>(agts, query_w, query_g, query_b, ctx_w1, agt_w);// launch 2
    k_nodes_b<<<256, NT>>>(ctx, ctx_w1);                                   // launch 3
    k_edge_mma<<<NE / TRE, 256, SMEM_EDGE>>>(agt_ctrs, ctx_ctrs, hi, wi,   // launch 4 (ncu)
                                             dist_w1, dist_b1,
                                             dist_g2, dist_b2,
                                             ctx_g1, ctx_b1);
    k_final<<<NA / TR, NT>>>(agts, norm_g, norm_b, lin_w, lin_g, lin_b, out);
}

// round 16
// speedup vs baseline: 1.6747x; 1.0087x over previous
#include <cuda_runtime.h>
#include <cuda_bf16.h>
#include <cuda_fp16.h>
#include <cstdint>

#define D     128
#define NA    16384
#define NC    16384
#define NE    524288
#define TR    64
#define NT    256
#define KC    16
#define TRE   128     // edges per block (4 row-groups x 32 rows, 2 col-halves; 8 warps)
#define EPS   1e-5f
#define AROWH 68      // u32 (half2) words per Aex row; 68 mod 32 = 4 -> conflict-free

// ---------------------------------------------------------------------------
// device scratch (no allocation)
// ---------------------------------------------------------------------------
__device__ __align__(16) uint32_t g_qbh[NA * 64];   // fp16: relu(GN(agts@query_w)) @ ctx_w1[128:256]
__device__ __align__(16) uint32_t g_ctxh[NC * 64];  // fp16: ctx @ ctx_w1[256:384]
__device__ __align__(16) float g_acc[NA * D];       // agts@agt_w + scattered edge output
__device__ __align__(16) uint32_t g_wt[3 * 8192];   // fp16 W images, FRAGMENT-ORDERED (32KB each)

// ---------------------------------------------------------------------------
// helpers
// ---------------------------------------------------------------------------
__device__ __forceinline__ uint32_t smem_u32(const void* p) {
    uint32_t a;
    asm("{ .reg .u64 t; cvta.to.shared.u64 t, %1; cvt.u32.u64 %0, t; }" : "=r"(a) : "l"(p));
    return a;
}

__device__ __forceinline__ uint32_t h2pack(float x0, float x1) {
    __half2 h = __floats2half2_rn(x0, x1);
    return *reinterpret_cast<uint32_t*>(&h);
}
__device__ __forceinline__ float2 h2unpack(uint32_t u) {
    __half2 h = *reinterpret_cast<__half2*>(&u);
    return __half22float2(h);
}

__device__ __forceinline__ void mma_f16(float c[4], const uint32_t a[4], uint32_t b0, uint32_t b1) {
    asm volatile(
        "mma.sync.aligned.m16n8k16.row.col.f32.f16.f16.f32 "
        "{%0,%1,%2,%3}, {%4,%5,%6,%7}, {%8,%9}, {%0,%1,%2,%3};"
        : "+f"(c[0]), "+f"(c[1]), "+f"(c[2]), "+f"(c[3])
        : "r"(a[0]), "r"(a[1]), "r"(a[2]), "r"(a[3]), "r"(b0), "r"(b1));
}

__device__ __forceinline__ uint32_t lds32(uint32_t a) {
    uint32_t v;
    asm volatile("ld.shared.b32 %0, [%1];" : "=r"(v) : "r"(a));
    return v;
}
__device__ __forceinline__ float lds32f(uint32_t a) {
    float v;
    asm volatile("ld.shared.f32 %0, [%1];" : "=f"(v) : "r"(a));
    return v;
}
__device__ __forceinline__ void sts32(uint32_t a, uint32_t x) {
    asm volatile("st.shared.b32 [%0], %1;" :: "r"(a), "r"(x) : "memory");
}

__device__ __forceinline__ void red4(float* p, float a, float b, float c, float d) {
    asm volatile("red.global.add.v4.f32 [%0], {%1,%2,%3,%4};"
                 :: "l"(p), "f"(a), "f"(b), "f"(c), "f"(d) : "memory");
}

// ---------------------------------------------------------------------------
// k_edge smem map (bytes): NO W buffer — B comes from L1 via LDG
// ---------------------------------------------------------------------------
#define SM_AEX    0        /* 128 rows x AROWH u32 = 34816B */
#define SM_STATS  34816    /* 512 floats */
#define SM_GB     36864    /* 512 floats: g2,b2,cg1,cb1 */
#define SM_HIS    38912
#define SM_WIS    39424
#define SM_D2     39936
#define SMEM_EDGE 40960

// Fragment-ordered fp16 W image for mma.m16n8k16 (row.col):
//   element (k, n):
//     kc = k>>4, kl = k&15, bk = (kl>>1)&3, h = kl&1, kh = kl>>3
//     nh = n>>6, p = (n>>3)&7, bn = n&7
//     lane = bn*4 + bk;  j = kh*2 + (p>>2);  e = p&3
//   u32 index within matrix = nh*4096 + kc*512 + j*128 + lane*4 + e; half h within.
__global__ void k_prep(const float* __restrict__ w0, const float* __restrict__ w1,
                       const float* __restrict__ w2) {
    int m = blockIdx.y;
    const float* src = (m == 0) ? w0 : (m == 1 ? w1 : w2);
    int idx = blockIdx.x * 256 + threadIdx.x;    // k*128 + n
    int k = idx >> 7, n = idx & 127;
    int kc = k >> 4, kl = k & 15;
    int bk = (kl >> 1) & 3, h = kl & 1, kh = kl >> 3;
    int nh = n >> 6, p = (n >> 3) & 7, bn = n & 7;
    int j = kh * 2 + (p >> 2);
    int e = p & 3;
    int l = bn * 4 + bk;
    int du = nh * 4096 + kc * 512 + j * 128 + l * 4 + e;
    __half hv = __float2half_rn(src[idx]);
    ((uint16_t*)(g_wt + m * 8192))[du * 2 + h] = *reinterpret_cast<uint16_t*>(&hv);
}

// C[2 mg][8 tiles][4] += A[32 rows, fp16 in smem] @ W[fp16 B frags via LDG from L1]
// warp rows rg*32..+31, cols nh*64..+63.  8 k16-chunks.
__device__ __forceinline__ void mma_stage(float c[2][8][4], uint32_t sb,
                                          const uint4* __restrict__ wg,
                                          int rg, int nh, int l) {
    const int ar = l >> 2, bk = l & 3;
    const uint32_t a0base = sb + SM_AEX + (uint32_t)(((rg * 32 + ar) * AROWH + bk) * 4);
    const uint4* bbase = wg + nh * 1024 + l;   // uint4 idx: nh*1024 + kc*128 + j*32 + l
#pragma unroll
    for (int kc = 0; kc < 8; kc++) {
        uint32_t a[2][4];
#pragma unroll
        for (int mg = 0; mg < 2; mg++) {
            uint32_t aa = a0base + (uint32_t)(mg * 16 * AROWH * 4 + kc * 32);
            a[mg][0] = lds32(aa);
            a[mg][2] = lds32(aa + 16);
            a[mg][1] = lds32(aa + 8 * AROWH * 4);
            a[mg][3] = lds32(aa + 8 * AROWH * 4 + 16);
        }
        {   // p = 0..3
            uint4 B0 = __ldg(bbase + kc * 128);        // b0 p0..3
            uint4 B2 = __ldg(bbase + kc * 128 + 64);   // b1 p0..3
            mma_f16(c[0][0], a[0], B0.x, B2.x);
            mma_f16(c[0][1], a[0], B0.y, B2.y);
            mma_f16(c[0][2], a[0], B0.z, B2.z);
            mma_f16(c[0][3], a[0], B0.w, B2.w);
            mma_f16(c[1][0], a[1], B0.x, B2.x);
            mma_f16(c[1][1], a[1], B0.y, B2.y);
            mma_f16(c[1][2], a[1], B0.z, B2.z);
            mma_f16(c[1][3], a[1], B0.w, B2.w);
        }
        {   // p = 4..7
            uint4 B1 = __ldg(bbase + kc * 128 + 32);   // b0 p4..7
            uint4 B3 = __ldg(bbase + kc * 128 + 96);   // b1 p4..7
            mma_f16(c[0][4], a[0], B1.x, B3.x);
            mma_f16(c[0][5], a[0], B1.y, B3.y);
            mma_f16(c[0][6], a[0], B1.z, B3.z);
            mma_f16(c[0][7], a[0], B1.w, B3.w);
            mma_f16(c[1][4], a[1], B1.x, B3.x);
            mma_f16(c[1][5], a[1], B1.y, B3.y);
            mma_f16(c[1][6], a[1], B1.z, B3.z);
            mma_f16(c[1][7], a[1], B1.w, B3.w);
        }
    }
}

// GN(+relu) epilogue: (gather fp16 tables) -> stats -> barrier -> normalize
// (gb from smem) -> Aex(fp16 pairs) -> barrier
template <bool GATHER>
__device__ __forceinline__ void ep_gn(float c[2][8][4],
                                      uint32_t gboff,   // smem byte offset of gamma (beta at +512)
                                      uint32_t sb, char* smem,
                                      const int* hi_s, const int* wi_s,
                                      int rg, int nh, int l) {
    const int q = l & 3;
    const int ar = l >> 2;
    const int cb = nh * 64;

    if (GATHER) {
        const int wq = (cb >> 1) + q;   // half2-word offset of this lane's first col pair
#pragma unroll
        for (int mg = 0; mg < 2; mg++) {
            int r0 = rg * 32 + mg * 16 + ar;
            const uint32_t* qA = g_qbh  + hi_s[r0] * 64 + wq;
            const uint32_t* cA = g_ctxh + wi_s[r0] * 64 + wq;
            const uint32_t* qB = g_qbh  + hi_s[r0 + 8] * 64 + wq;
            const uint32_t* cB = g_ctxh + wi_s[r0 + 8] * 64 + wq;
#pragma unroll
            for (int t = 0; t < 8; t++) {
                float2 a1 = h2unpack(__ldg(qA + t * 4));
                float2 a2 = h2unpack(__ldg(cA + t * 4));
                float2 b1 = h2unpack(__ldg(qB + t * 4));
                float2 b2 = h2unpack(__ldg(cB + t * 4));
                c[mg][t][0] += a1.x + a2.x;  c[mg][t][1] += a1.y + a2.y;
                c[mg][t][2] += b1.x + b2.x;  c[mg][t][3] += b1.y + b2.y;
            }
        }
    }
    float s[4] = {0.f, 0.f, 0.f, 0.f}, qs[4] = {0.f, 0.f, 0.f, 0.f};
#pragma unroll
    for (int mg = 0; mg < 2; mg++)
#pragma unroll
        for (int t = 0; t < 8; t++) {
            s[mg * 2]     += c[mg][t][0] + c[mg][t][1];
            qs[mg * 2]     = fmaf(c[mg][t][0], c[mg][t][0], fmaf(c[mg][t][1], c[mg][t][1], qs[mg * 2]));
            s[mg * 2 + 1] += c[mg][t][2] + c[mg][t][3];
            qs[mg * 2 + 1] = fmaf(c[mg][t][2], c[mg][t][2], fmaf(c[mg][t][3], c[mg][t][3], qs[mg * 2 + 1]));
        }
#pragma unroll
    for (int i = 0; i < 4; i++) {
        s[i]  += __shfl_xor_sync(~0u, s[i], 1);  s[i]  += __shfl_xor_sync(~0u, s[i], 2);
        qs[i] += __shfl_xor_sync(~0u, qs[i], 1); qs[i] += __shfl_xor_sync(~0u, qs[i], 2);
    }

    float* st = (float*)(smem + SM_STATS);   // [nh][sum(128) | sq(128)]
    if (q == 0) {
#pragma unroll
        for (int mg = 0; mg < 2; mg++) {
            int r0 = rg * 32 + mg * 16 + ar;
            st[nh * 256 + r0]           = s[mg * 2];
            st[nh * 256 + 128 + r0]     = qs[mg * 2];
            st[nh * 256 + r0 + 8]       = s[mg * 2 + 1];
            st[nh * 256 + 128 + r0 + 8] = qs[mg * 2 + 1];
        }
    }
    __syncthreads();   // stats visible; all Aex reads of this stage done

#pragma unroll
    for (int mg = 0; mg < 2; mg++) {
        int rA = rg * 32 + mg * 16 + ar;
        int rB = rA + 8;
        float S   = st[rA] + st[256 + rA];
        float SQ  = st[128 + rA] + st[384 + rA];
        float Sb  = st[rB] + st[256 + rB];
        float SQb = st[128 + rB] + st[384 + rB];
        float mA = S  * (1.f / 128.f), vA = SQ  * (1.f / 128.f) - mA * mA, rsA = rsqrtf(vA + EPS);
        float mB = Sb * (1.f / 128.f), vB = SQb * (1.f / 128.f) - mB * mB, rsB = rsqrtf(vB + EPS);
#pragma unroll
        for (int t = 0; t < 8; t++) {
            int c0 = cb + t * 8 + q * 2;
            float g0 = lds32f(sb + gboff + (uint32_t)(c0 * 4));
            float g1 = lds32f(sb + gboff + (uint32_t)(c0 * 4) + 4);
            float b0 = lds32f(sb + gboff + 512u + (uint32_t)(c0 * 4));
            float b1 = lds32f(sb + gboff + 512u + (uint32_t)(c0 * 4) + 4);
            float xA0 = fmaxf(fmaf((c[mg][t][0] - mA) * rsA, g0, b0), 0.f);
            float xA1 = fmaxf(fmaf((c[mg][t][1] - mA) * rsA, g1, b1), 0.f);
            float xB0 = fmaxf(fmaf((c[mg][t][2] - mB) * rsB, g0, b0), 0.f);
            float xB1 = fmaxf(fmaf((c[mg][t][3] - mB) * rsB, g1, b1), 0.f);
            int wA = rA * AROWH + (c0 >> 1);
            int wB = rB * AROWH + (c0 >> 1);
            sts32(sb + SM_AEX + (uint32_t)(wA * 4), h2pack(xA0, xA1));
            sts32(sb + SM_AEX + (uint32_t)(wB * 4), h2pack(xB0, xB1));
        }
    }
    __syncthreads();   // Aex visible
}

__global__ __launch_bounds__(256, 2) void k_edge_mma(
    const float* __restrict__ agt_ctrs, const float* __restrict__ ctx_ctrs,
    const int* __restrict__ hi, const int* __restrict__ wi,
    const float* __restrict__ dist_w1, const float* __restrict__ dist_b1,
    const float* __restrict__ dist_g2, const float* __restrict__ dist_b2,
    const float* __restrict__ ctx_g1, const float* __restrict__ ctx_b1) {
    extern __shared__ char smem[];
    const uint32_t sb = smem_u32(smem);
    const int tid = threadIdx.x;
    const int w = tid >> 5, l = tid & 31;
    const int rg = w >> 1, nh = w & 1;         // row group 0-3 (32 rows), col half 0-1
    const int ar = l >> 2;

    int* hi_s = (int*)(smem + SM_HIS);
    int* wi_s = (int*)(smem + SM_WIS);
    float2* d2s = (float2*)(smem + SM_D2);
    float* gbs = (float*)(smem + SM_GB);
    const int e0 = blockIdx.x * TRE;
    if (tid < TRE) {
        int h = hi[e0 + tid], ww = wi[e0 + tid];
        hi_s[tid] = h; wi_s[tid] = ww;
        float2 ac = ((const float2*)agt_ctrs)[h];
        float2 cc = ((const float2*)ctx_ctrs)[ww];
        d2s[tid] = make_float2(ac.x - cc.x, ac.y - cc.y);
    }
    // gamma/beta stash: [0:128) g2 [128:256) b2 [256:384) cg1 [384:512) cb1
    gbs[tid]       = (tid < 128) ? __ldg(dist_g2 + tid) : __ldg(dist_b2 + tid - 128);
    gbs[256 + tid] = (tid < 128) ? __ldg(ctx_g1 + tid)  : __ldg(ctx_b1 + tid - 128);
    __syncthreads();                           // ids/d2/gb visible

    // initial A = relu(d2 @ dist_w1 + b1) -> Aex as half2 words
    for (int idx = tid; idx < TRE * 64; idx += 256) {
        int row = idx >> 6, wrd = idx & 63;
        int c2 = wrd * 2;
        float2 dd = d2s[row];
        float2 w0v = __ldg((const float2*)(dist_w1 + c2));
        float2 w1v = __ldg((const float2*)(dist_w1 + D + c2));
        float2 bbv = __ldg((const float2*)(dist_b1 + c2));
        float x0 = fmaxf(fmaf(dd.x, w0v.x, fmaf(dd.y, w1v.x, bbv.x)), 0.f);
        float x1 = fmaxf(fmaf(dd.x, w0v.y, fmaf(dd.y, w1v.y, bbv.y)), 0.f);
        sts32(sb + SM_AEX + (uint32_t)((row * AROWH + wrd) * 4), h2pack(x0, x1));
    }
    __syncthreads();                           // Aex visible

    float c[2][8][4];
    // ---- stage 1: @ dist_w2, GN(dist_g2,b2)+relu ----
#pragma unroll
    for (int mg = 0; mg < 2; mg++)
#pragma unroll
        for (int t = 0; t < 8; t++)
            c[mg][t][0] = c[mg][t][1] = c[mg][t][2] = c[mg][t][3] = 0.f;
    mma_stage(c, sb, (const uint4*)g_wt, rg, nh, l);
    ep_gn<false>(c, SM_GB, sb, smem, hi_s, wi_s, rg, nh, l);

    // ---- stage 2: @ ctx_w1[0:128] + qb[hi] + ctxc[wi], GN(ctx_g1,b1)+relu ----
#pragma unroll
    for (int mg = 0; mg < 2; mg++)
#pragma unroll
        for (int t = 0; t < 8; t++)
            c[mg][t][0] = c[mg][t][1] = c[mg][t][2] = c[mg][t][3] = 0.f;
    mma_stage(c, sb, (const uint4*)(g_wt + 8192), rg, nh, l);
    ep_gn<true>(c, SM_GB + 1024, sb, smem, hi_s, wi_s, rg, nh, l);

    // ---- stage 3: @ ctx_w2, scatter-add ----
#pragma unroll
    for (int mg = 0; mg < 2; mg++)
#pragma unroll
        for (int t = 0; t < 8; t++)
            c[mg][t][0] = c[mg][t][1] = c[mg][t][2] = c[mg][t][3] = 0.f;
    mma_stage(c, sb, (const uint4*)(g_wt + 16384), rg, nh, l);
    {
        const int q2 = l & 3;
        const bool even = (q2 & 1) == 0;
#pragma unroll
        for (int mg = 0; mg < 2; mg++) {
            int r0 = rg * 32 + mg * 16 + ar;
            float* baseA = g_acc + hi_s[r0] * D + nh * 64;
            float* baseB = g_acc + hi_s[r0 + 8] * D + nh * 64;
#pragma unroll
            for (int t = 0; t < 8; t++) {
                float x0 = __shfl_xor_sync(~0u, c[mg][t][0], 1);
                float x1 = __shfl_xor_sync(~0u, c[mg][t][1], 1);
                float x2 = __shfl_xor_sync(~0u, c[mg][t][2], 1);
                float x3 = __shfl_xor_sync(~0u, c[mg][t][3], 1);
                if (even) red4(baseA + t * 8 + q2 * 2,       c[mg][t][0], c[mg][t][1], x0, x1);
                else      red4(baseB + t * 8 + (q2 - 1) * 2, x2, x3, c[mg][t][2], c[mg][t][3]);
            }
        }
    }
}

// ---------------------------------------------------------------------------
// FFMA node kernels (split so k_edge is launch #4 for ncu)
// ---------------------------------------------------------------------------
__device__ __forceinline__ void gemm_tile(const float* in_s, const float* __restrict__ W,
                                          float* wbuf, float acc[8][4], int e0, int c4, int tid) {
    const float4* Wg = reinterpret_cast<const float4*>(W);
    float4* wb = reinterpret_cast<float4*>(wbuf);
    for (int kb = 0; kb < D; kb += KC) {
        __syncthreads();
        wb[tid]      = Wg[kb * (D / 4) + tid];
        wb[tid + NT] = Wg[kb * (D / 4) + tid + NT];
        __syncthreads();
#pragma unroll
        for (int kk = 0; kk < KC; kk++) {
            float4 w = wb[kk * (D / 4) + c4];
#pragma unroll
            for (int i = 0; i < 8; i++) {
                float h = in_s[(e0 + i) * D + kb + kk];
                acc[i][0] = fmaf(h, w.x, acc[i][0]);
                acc[i][1] = fmaf(h, w.y, acc[i][1]);
                acc[i][2] = fmaf(h, w.z, acc[i][2]);
                acc[i][3] = fmaf(h, w.w, acc[i][3]);
            }
        }
    }
}

__device__ __forceinline__ void zero_acc(float acc[8][4]) {
#pragma unroll
    for (int i = 0; i < 8; i++)
#pragma unroll
        for (int j = 0; j < 4; j++) acc[i][j] = 0.f;
}

__device__ __forceinline__ void store_acc(float* io, const float acc[8][4], int e0, int c4) {
#pragma unroll
    for (int i = 0; i < 8; i++) {
        float4 v = make_float4(acc[i][0], acc[i][1], acc[i][2], acc[i][3]);
        *reinterpret_cast<float4*>(&io[(e0 + i) * D + c4 * 4]) = v;
    }
}

// store acc to a half2 table (word idx = row*64 + c4*2)
__device__ __forceinline__ void store_acc_h2(uint32_t* table, const float acc[8][4], int r0, int e0, int c4) {
#pragma unroll
    for (int i = 0; i < 8; i++) {
        uint2 v = make_uint2(h2pack(acc[i][0], acc[i][1]), h2pack(acc[i][2], acc[i][3]));
        *reinterpret_cast<uint2*>(&table[(r0 + e0 + i) * 64 + c4 * 2]) = v;
    }
}

__device__ __forceinline__ void gn_rows(float* io, const float* __restrict__ g,
                                        const float* __restrict__ b, bool do_relu, int tid) {
    int lane = tid & 31, w = tid >> 5;
    for (int r = w; r < TR; r += 8) {
        float v[4], s = 0.f, sq = 0.f;
#pragma unroll
        for (int j = 0; j < 4; j++) {
            v[j] = io[r * D + lane + 32 * j];
            s += v[j]; sq += v[j] * v[j];
        }
#pragma unroll
        for (int o = 16; o > 0; o >>= 1) {
            s  += __shfl_xor_sync(0xffffffffu, s, o);
            sq += __shfl_xor_sync(0xffffffffu, sq, o);
        }
        float mean = s * (1.f / D);
        float var  = sq * (1.f / D) - mean * mean;
        float rstd = rsqrtf(var + EPS);
#pragma unroll
        for (int j = 0; j < 4; j++) {
            int c = lane + 32 * j;
            float x = (v[j] - mean) * rstd * g[c] + b[c];
            io[r * D + c] = do_relu ? fmaxf(x, 0.f) : x;
        }
    }
}

__global__ __launch_bounds__(NT) void k_nodes_a(const float* __restrict__ agts,
                                                const float* __restrict__ query_w,
                                                const float* __restrict__ query_g,
                                                const float* __restrict__ query_b,
                                                const float* __restrict__ ctx_w1,
                                                const float* __restrict__ agt_w) {
    __shared__ float io[TR * D];
    __shared__ float wbuf[KC * D];
    int tid = threadIdx.x;
    int task = blockIdx.x >> 8;
    int r0 = (blockIdx.x & 255) * TR;
    int lane = tid & 31, wid = tid >> 5;
    int c4 = lane, e0 = wid * 8;
    float acc[8][4];

    for (int idx = tid; idx < TR * D; idx += NT) io[idx] = agts[r0 * D + idx];

    if (task == 0) {
        zero_acc(acc);
        gemm_tile(io, query_w, wbuf, acc, e0, c4, tid);
        __syncthreads();
        store_acc(io, acc, e0, c4);
        __syncthreads();
        gn_rows(io, query_g, query_b, true, tid);
        __syncthreads();
        zero_acc(acc);
        gemm_tile(io, ctx_w1 + D * D, wbuf, acc, e0, c4, tid);
        store_acc_h2(g_qbh, acc, r0, e0, c4);
    } else {
        zero_acc(acc);
        gemm_tile(io, agt_w, wbuf, acc, e0, c4, tid);
#pragma unroll
        for (int i = 0; i < 8; i++) {
            float4 v = make_float4(acc[i][0], acc[i][1], acc[i][2], acc[i][3]);
            *reinterpret_cast<float4*>(&g_acc[(r0 + e0 + i) * D + c4 * 4]) = v;
        }
    }
}

__global__ __launch_bounds__(NT) void k_nodes_b(const float* __restrict__ ctx,
                                                const float* __restrict__ ctx_w1) {
    __shared__ float io[TR * D];
    __shared__ float wbuf[KC * D];
    int tid = threadIdx.x;
    int r0 = blockIdx.x * TR;
    int lane = tid & 31, wid = tid >> 5;
    int c4 = lane, e0 = wid * 8;
    float acc[8][4];

    for (int idx = tid; idx < TR * D; idx += NT) io[idx] = ctx[r0 * D + idx];
    zero_acc(acc);
    gemm_tile(io, ctx_w1 + 2 * D * D, wbuf, acc, e0, c4, tid);
    store_acc_h2(g_ctxh, acc, r0, e0, c4);
}

__global__ __launch_bounds__(NT) void k_final(const float* __restrict__ agts,
                                              const float* __restrict__ norm_g,
                                              const float* __restrict__ norm_b,
                                              const float* __restrict__ lin_w,
                                              const float* __restrict__ lin_g,
                                              const float* __restrict__ lin_b,
                                              float* __restrict__ out) {
    __shared__ float io[TR * D];
    __shared__ float wbuf[KC * D];
    int tid = threadIdx.x;
    int r0 = blockIdx.x * TR;
    int lane = tid & 31, wid = tid >> 5;
    int c4 = lane, e0 = wid * 8;

    for (int idx = tid; idx < TR * D; idx += NT) io[idx] = g_acc[r0 * D + idx];
    __syncthreads();
    gn_rows(io, norm_g, norm_b, true, tid);
    __syncthreads();

    float acc[8][4];
    zero_acc(acc);
    gemm_tile(io, lin_w, wbuf, acc, e0, c4, tid);
    __syncthreads();
    store_acc(io, acc, e0, c4);
    __syncthreads();

    for (int r = wid; r < TR; r += 8) {
        float v[4], s = 0.f, sq = 0.f;
#pragma unroll
        for (int j = 0; j < 4; j++) {
            v[j] = io[r * D + lane + 32 * j];
            s += v[j]; sq += v[j] * v[j];
        }
#pragma unroll
        for (int o = 16; o > 0; o >>= 1) {
            s  += __shfl_xor_sync(0xffffffffu, s, o);
            sq += __shfl_xor_sync(0xffffffffu, sq, o);
        }
        float mean = s * (1.f / D);
        float var  = sq * (1.f / D) - mean * mean;
        float rstd = rsqrtf(var + EPS);
#pragma unroll
        for (int j = 0; j < 4; j++) {
            int c = lane + 32 * j;
            float x = (v[j] - mean) * rstd * lin_g[c] + lin_b[c];
            float res = agts[(r0 + r) * D + c];
            out[(r0 + r) * D + c] = fmaxf(x + res, 0.f);
        }
    }
}

// ---------------------------------------------------------------------------
extern "C" void kernel_launch(void* const* d_in, const int* in_sizes, int n_in,
                              void* d_out, int out_size) {
    const float* agts     = (const float*)d_in[0];
    const float* ctx      = (const float*)d_in[1];
    const float* agt_ctrs = (const float*)d_in[2];
    const float* ctx_ctrs = (const float*)d_in[3];
    const int*   hi       = (const int*)d_in[4];
    const int*   wi       = (const int*)d_in[5];
    const float* dist_w1  = (const float*)d_in[6];
    const float* dist_b1  = (const float*)d_in[7];
    const float* dist_w2  = (const float*)d_in[8];
    const float* dist_g2  = (const float*)d_in[9];
    const float* dist_b2  = (const float*)d_in[10];
    const float* query_w  = (const float*)d_in[11];
    const float* query_g  = (const float*)d_in[12];
    const float* query_b  = (const float*)d_in[13];
    const float* ctx_w1   = (const float*)d_in[14];
    const float* ctx_g1   = (const float*)d_in[15];
    const float* ctx_b1   = (const float*)d_in[16];
    const float* ctx_w2   = (const float*)d_in[17];
    const float* agt_w    = (const float*)d_in[18];
    const float* norm_g   = (const float*)d_in[19];
    const float* norm_b   = (const float*)d_in[20];
    const float* lin_w    = (const float*)d_in[21];
    const float* lin_g    = (const float*)d_in[22];
    const float* lin_b    = (const float*)d_in[23];
    float* out = (float*)d_out;

    cudaFuncSetAttribute(k_edge_mma, cudaFuncAttributeMaxDynamicSharedMemorySize, SMEM_EDGE);

    k_prep<<<dim3(64, 3), 256>>>(dist_w2, ctx_w1, ctx_w2);                 // launch 1
    k_nodes_a<<<512, NT>>>(agts, query_w, query_g, query_b, ctx_w1, agt_w);// launch 2
    k_nodes_b<<<256, NT>>>(ctx, ctx_w1);                                   // launch 3
    k_edge_mma<<<NE / TRE, 256, SMEM_EDGE>>>(agt_ctrs, ctx_ctrs, hi, wi,   // launch 4 (ncu)
                                             dist_w1, dist_b1,
                                             dist_g2, dist_b2,
                                             ctx_g1, ctx_b1);
    k_final<<<NA / TR, NT>>>(agts, norm_g, norm_b, lin_w, lin_g, lin_b, out);
}